// round 4
// baseline (speedup 1.0000x reference)
#include <cuda_runtime.h>
#include <cstddef>

typedef unsigned int u32;
typedef unsigned long long ull;

#define NROWS 65536
#define F1 48
#define F2 24
#define F3 10
#define KDIM 784
#define EPSBN 1e-5f
#define KC 28
#define XST 132

// ----------------------------- device scratch -----------------------------
__device__ float g_Y1[(size_t)NROWS * F1];
__device__ float g_Y2[(size_t)NROWS * F2];
__device__ float g_p1s[512 * F1];
__device__ float g_p1q[512 * F1];
__device__ float g_p2s[2048 * F2];
__device__ float g_p2q[2048 * F2];
__device__ float g_scale1[F1], g_shift1[F1];
__device__ float g_scale2[F2], g_shift2[F2];
__device__ float g_na1, g_nm1, g_na2, g_nm2;
__device__ u32   g_k1a, g_k1b, g_k2a, g_k2b;

// ----------------------------- helpers ------------------------------------
__device__ __forceinline__ ull f2fma(ull a, ull b, ull c) {
    ull d;
    asm("fma.rn.f32x2 %0, %1, %2, %3;" : "=l"(d) : "l"(a), "l"(b), "l"(c));
    return d;
}
__device__ __forceinline__ ull pack2(float lo, float hi) {
    ull r;
    asm("mov.b64 %0, {%1, %2};" : "=l"(r) : "f"(lo), "f"(hi));
    return r;
}
__device__ __forceinline__ void unpack2(ull v, float &lo, float &hi) {
    asm("mov.b64 {%0, %1}, %2;" : "=f"(lo), "=f"(hi) : "l"(v));
}

// Threefry-2x32, 20 rounds.
__device__ __forceinline__ void tf2x32(u32 k0, u32 k1, u32 x0, u32 x1,
                                       u32 &o0, u32 &o1) {
    u32 k2 = k0 ^ k1 ^ 0x1BD11BDAu;
    x0 += k0; x1 += k1;
#define TF_R(r) { x0 += x1; x1 = __funnelshift_l(x1, x1, (r)); x1 ^= x0; }
    TF_R(13) TF_R(15) TF_R(26) TF_R(6)   x0 += k1; x1 += k2 + 1u;
    TF_R(17) TF_R(29) TF_R(16) TF_R(24)  x0 += k2; x1 += k0 + 2u;
    TF_R(13) TF_R(15) TF_R(26) TF_R(6)   x0 += k0; x1 += k1 + 3u;
    TF_R(17) TF_R(29) TF_R(16) TF_R(24)  x0 += k1; x1 += k2 + 4u;
    TF_R(13) TF_R(15) TF_R(26) TF_R(6)   x0 += k2; x1 += k0 + 5u;
#undef TF_R
    o0 = x0; o1 = x1;
}

// jax.random.normal(f32) from 32 bits: u in [-1+2^-24, 1), sqrt(2)*erfinv(u)
// erfinv = XLA's Giles polynomial (exact constants).
__device__ __forceinline__ float jax_normal(u32 bits) {
    float u01 = __uint_as_float((bits >> 9) | 0x3f800000u) - 1.0f;
    float u   = fmaxf(-0.99999994f, fmaf(u01, 2.0f, -0.99999994f));
    float w   = -log1pf(-u * u);
    float p;
    if (w < 5.0f) {
        w -= 2.5f;
        p = 2.81022636e-08f;
        p = fmaf(p, w, 3.43273939e-07f);
        p = fmaf(p, w, -3.5233877e-06f);
        p = fmaf(p, w, -4.39150654e-06f);
        p = fmaf(p, w, 0.00021858087f);
        p = fmaf(p, w, -0.00125372503f);
        p = fmaf(p, w, -0.00417768164f);
        p = fmaf(p, w, 0.246640727f);
        p = fmaf(p, w, 1.50140941f);
    } else {
        w = sqrtf(w) - 3.0f;
        p = -0.000200214257f;
        p = fmaf(p, w, 0.000100950558f);
        p = fmaf(p, w, 0.00134934322f);
        p = fmaf(p, w, -0.00367342844f);
        p = fmaf(p, w, 0.00573950773f);
        p = fmaf(p, w, -0.0076224613f);
        p = fmaf(p, w, 0.00943887047f);
        p = fmaf(p, w, 1.00167406f);
        p = fmaf(p, w, 2.83297682f);
    }
    return 1.41421356f * (p * u);
}

// ----------------------------- K1: Y1 = x @ w1^T + b1 ---------------------
// 512 blocks x 128 threads; block tile 128 rows x 48 cols; f32x2 packed FMA.
__global__ void __launch_bounds__(128) k1_gemm(const float* __restrict__ x,
                                               const float* __restrict__ w1,
                                               const float* __restrict__ b1) {
    __shared__ float  xs[KC * XST];     // transposed x chunk [k][row]
    __shared__ float2 ws[KC * F1];      // duplicated w chunk [k][col]
    __shared__ float  red[2 * 16 * F1]; // stats reduction

    int tid  = threadIdx.x;
    int m_id = tid >> 3, n_id = tid & 7;
    int m8 = m_id * 8, n6 = n_id * 6;
    int rowBase = blockIdx.x * 128;

    ull acc[4][6];
#pragma unroll
    for (int c = 0; c < 6; c++) {
        float b = b1[n6 + c];
        ull pb = pack2(b, b);
#pragma unroll
        for (int j = 0; j < 4; j++) acc[j][c] = pb;
    }

    const float4* xg = (const float4*)(x + (size_t)rowBase * KDIM);

    for (int k0 = 0; k0 < KDIM; k0 += KC) {
        __syncthreads();
        // x chunk: 128 rows x 28 k, via float4, stored transposed
        int kq0 = k0 >> 2;  // float4 offset of k0 within a row
#pragma unroll
        for (int p = 0; p < 7; p++) {
            int i = p * 128 + tid;           // 0..895
            int r = i / 7, q = i - r * 7;
            float4 v = xg[(size_t)r * 196 + kq0 + q];
            int kk = q * 4;
            xs[kk * XST + r]       = v.x;
            xs[(kk + 1) * XST + r] = v.y;
            xs[(kk + 2) * XST + r] = v.z;
            xs[(kk + 3) * XST + r] = v.w;
        }
        // w chunk: 48 cols x 28 k, duplicated
        for (int i = tid; i < F1 * KC; i += 128) {
            int c = i / KC, kk = i - c * KC;
            float wv = w1[c * KDIM + k0 + kk];
            ws[kk * F1 + c] = make_float2(wv, wv);
        }
        __syncthreads();
#pragma unroll
        for (int kk = 0; kk < KC; kk++) {
            ull xv[4], wv[6];
#pragma unroll
            for (int j = 0; j < 4; j++)
                xv[j] = *(const ull*)&xs[kk * XST + m8 + 2 * j];
#pragma unroll
            for (int c = 0; c < 6; c++)
                wv[c] = *(const ull*)&ws[kk * F1 + n6 + c];
#pragma unroll
            for (int j = 0; j < 4; j++)
#pragma unroll
                for (int c = 0; c < 6; c++)
                    acc[j][c] = f2fma(xv[j], wv[c], acc[j][c]);
        }
    }

    // epilogue: write Y1 + per-column partial stats
    float s[6], q[6];
#pragma unroll
    for (int c = 0; c < 6; c++) { s[c] = 0.f; q[c] = 0.f; }
#pragma unroll
    for (int j = 0; j < 4; j++) {
        float lo[6], hi[6];
#pragma unroll
        for (int c = 0; c < 6; c++) unpack2(acc[j][c], lo[c], hi[c]);
        float* y0 = g_Y1 + (size_t)(rowBase + m8 + 2 * j) * F1 + n6;
        float* y1 = y0 + F1;
#pragma unroll
        for (int c = 0; c < 3; c++) {
            ((float2*)y0)[c] = make_float2(lo[2 * c], lo[2 * c + 1]);
            ((float2*)y1)[c] = make_float2(hi[2 * c], hi[2 * c + 1]);
        }
#pragma unroll
        for (int c = 0; c < 6; c++) {
            s[c] += lo[c] + hi[c];
            q[c] += lo[c] * lo[c] + hi[c] * hi[c];
        }
    }
    __syncthreads();
#pragma unroll
    for (int c = 0; c < 6; c++) {
        red[m_id * F1 + n6 + c]            = s[c];
        red[16 * F1 + m_id * F1 + n6 + c]  = q[c];
    }
    __syncthreads();
    if (tid < F1) {
        float ss = 0.f, qq = 0.f;
        for (int m = 0; m < 16; m++) {
            ss += red[m * F1 + tid];
            qq += red[16 * F1 + m * F1 + tid];
        }
        g_p1s[blockIdx.x * F1 + tid] = ss;
        g_p1q[blockIdx.x * F1 + tid] = qq;
    }
}

// ----------------------------- K2: finalize layer-1 stats -----------------
__global__ void __launch_bounds__(512) k2_fin(const float* __restrict__ gamma,
                                              const float* __restrict__ beta) {
    __shared__ float sm[2 * 8 * F1];
    __shared__ float term[F1];
    __shared__ float betas[F1];
    int tid = threadIdx.x;
    int j = tid & 63, g = tid >> 6;
    if (j < F1) {
        float s = 0.f, q = 0.f;
        for (int b = g; b < 512; b += 8) {
            s += g_p1s[b * F1 + j];
            q += g_p1q[b * F1 + j];
        }
        sm[g * F1 + j]          = s;
        sm[8 * F1 + g * F1 + j] = q;
    }
    __syncthreads();
    if (tid < F1) {
        float ss = 0.f, qq = 0.f;
        for (int g2 = 0; g2 < 8; g2++) {
            ss += sm[g2 * F1 + tid];
            qq += sm[8 * F1 + g2 * F1 + tid];
        }
        float m = ss / 65536.0f;
        float v = fmaxf(qq / 65536.0f - m * m, 0.f);
        float ga = gamma[tid], be = beta[tid];
        float sc = ga * rsqrtf(v + EPSBN);
        g_scale1[tid] = sc;
        g_shift1[tid] = be - m * sc;
        betas[tid]    = be;
        term[tid]     = ga * ga * (v / (v + EPSBN));
    }
    __syncthreads();
    if (tid == 0) {
        float nb = 0.f;
        for (int c = 0; c < F1; c++) nb += betas[c];
        float nm = nb / (float)F1;
        float S = 0.f;
        for (int c = 0; c < F1; c++) {
            float d = betas[c] - nm;
            S += term[c] + d * d;
        }
        float var = (65536.0f * S) / (65536.0f * (float)F1 - 1.0f);
        float sdev = sqrtf(var);
        // key(1234); split -> ku=(ctr 0,0), kn=(ctr 0,1)
        u32 ka, kb, na, nbk;
        tf2x32(0u, 1234u, 0u, 0u, ka, kb);   // ku
        tf2x32(0u, 1234u, 0u, 1u, na, nbk);  // kn
        u32 u0, u1;
        tf2x32(ka, kb, 0u, 0u, u0, u1);
        u32 bits = u0 ^ u1;
        float u01 = __uint_as_float((bits >> 9) | 0x3f800000u) - 1.0f;
        float uu = fmaxf(1.0f, u01 + 1.0f);
        g_na1 = sdev * uu;
        g_nm1 = nm;
        g_k1a = na; g_k1b = nbk;
    }
}

// ----------------------------- K3: BN1+noise+ReLU -> GEMM2 ----------------
__global__ void __launch_bounds__(128) k3_mid(const float* __restrict__ w2,
                                              const float* __restrict__ b2) {
    __shared__ float ys[128 * 49];
    __shared__ float w2s[F2 * F1];
    __shared__ float b2s[F2];
    __shared__ float sc1[F1], sh1[F1];
    int tid = threadIdx.x;
    int rowBase = blockIdx.x * 128;

    for (int i = tid; i < F2 * F1; i += 128) w2s[i] = w2[i];
    if (tid < F2) b2s[tid] = b2[tid];
    if (tid < F1) { sc1[tid] = g_scale1[tid]; sh1[tid] = g_shift1[tid]; }
    {
        const float* yg = g_Y1 + (size_t)rowBase * F1;
        for (int i = tid; i < 128 * F1; i += 128) {
            int r = i / F1, c = i - r * F1;
            ys[r * 49 + c] = yg[i];
        }
    }
    __syncthreads();

    int row = rowBase + tid;
    float na = g_na1, nm = g_nm1;
    u32 ka = g_k1a, kb = g_k1b;
    u32 base = (u32)row * (u32)F1;

    float acc[F2];
#pragma unroll
    for (int j = 0; j < F2; j++) acc[j] = b2s[j];

#pragma unroll 4
    for (int c = 0; c < F1; c++) {
        float h = fmaf(ys[tid * 49 + c], sc1[c], sh1[c]);
        u32 o0, o1;
        tf2x32(ka, kb, 0u, base + (u32)c, o0, o1);
        float noi = fmaf(na, jax_normal(o0 ^ o1), nm);
        float zc = fmaxf(h + noi, 0.f);
#pragma unroll
        for (int j = 0; j < F2; j++)
            acc[j] = fmaf(zc, w2s[j * F1 + c], acc[j]);
    }

    // per-warp column stats of Y2
    int lane = tid & 31, wrp = tid >> 5;
#pragma unroll
    for (int j = 0; j < F2; j++) {
        float sv = acc[j], qv = acc[j] * acc[j];
#pragma unroll
        for (int off = 16; off > 0; off >>= 1) {
            sv += __shfl_down_sync(0xffffffffu, sv, off);
            qv += __shfl_down_sync(0xffffffffu, qv, off);
        }
        if (lane == 0) {
            int pb = blockIdx.x * 4 + wrp;
            g_p2s[pb * F2 + j] = sv;
            g_p2q[pb * F2 + j] = qv;
        }
    }

    // staged coalesced write of Y2
    __syncthreads();
#pragma unroll
    for (int j = 0; j < F2; j++) ys[tid * 25 + j] = acc[j];
    __syncthreads();
    {
        float* yg2 = g_Y2 + (size_t)rowBase * F2;
        for (int i = tid; i < 128 * F2; i += 128) {
            int r = i / F2, j = i - r * F2;
            yg2[i] = ys[r * 25 + j];
        }
    }
}

// ----------------------------- K4: finalize layer-2 stats -----------------
__global__ void __launch_bounds__(512) k4_fin(const float* __restrict__ gamma,
                                              const float* __restrict__ beta) {
    __shared__ float sm[2 * 16 * F2];
    __shared__ float term[F2];
    __shared__ float betas[F2];
    int tid = threadIdx.x;
    int j = tid & 31, g = tid >> 5;
    if (j < F2) {
        float s = 0.f, q = 0.f;
        for (int b = g; b < 2048; b += 16) {
            s += g_p2s[b * F2 + j];
            q += g_p2q[b * F2 + j];
        }
        sm[g * F2 + j]           = s;
        sm[16 * F2 + g * F2 + j] = q;
    }
    __syncthreads();
    if (tid < F2) {
        float ss = 0.f, qq = 0.f;
        for (int g2 = 0; g2 < 16; g2++) {
            ss += sm[g2 * F2 + tid];
            qq += sm[16 * F2 + g2 * F2 + tid];
        }
        float m = ss / 65536.0f;
        float v = fmaxf(qq / 65536.0f - m * m, 0.f);
        float ga = gamma[tid], be = beta[tid];
        float sc = ga * rsqrtf(v + EPSBN);
        g_scale2[tid] = sc;
        g_shift2[tid] = be - m * sc;
        betas[tid]    = be;
        term[tid]     = ga * ga * (v / (v + EPSBN));
    }
    __syncthreads();
    if (tid == 0) {
        float nb = 0.f;
        for (int c = 0; c < F2; c++) nb += betas[c];
        float nm = nb / (float)F2;
        float S = 0.f;
        for (int c = 0; c < F2; c++) {
            float d = betas[c] - nm;
            S += term[c] + d * d;
        }
        float var = (65536.0f * S) / (65536.0f * (float)F2 - 1.0f);
        float sdev = sqrtf(var);
        u32 ka, kb, na, nbk;
        tf2x32(0u, 5678u, 0u, 0u, ka, kb);   // ku
        tf2x32(0u, 5678u, 0u, 1u, na, nbk);  // kn
        u32 u0, u1;
        tf2x32(ka, kb, 0u, 0u, u0, u1);
        u32 bits = u0 ^ u1;
        float u01 = __uint_as_float((bits >> 9) | 0x3f800000u) - 1.0f;
        float uu = fmaxf(1.0f, u01 + 1.0f);
        g_na2 = sdev * uu;
        g_nm2 = nm;
        g_k2a = na; g_k2b = nbk;
    }
}

// ----------------------------- K5: BN2+noise+ReLU -> GEMM3 -> out ---------
__global__ void __launch_bounds__(128) k5_out(const float* __restrict__ w3,
                                              const float* __restrict__ b3,
                                              float* __restrict__ out) {
    __shared__ float ys[128 * 25];
    __shared__ float w3s[F3 * F2];
    __shared__ float b3s[F3];
    __shared__ float sc2[F2], sh2[F2];
    int tid = threadIdx.x;
    int rowBase = blockIdx.x * 128;

    for (int i = tid; i < F3 * F2; i += 128) w3s[i] = w3[i];
    if (tid < F3) b3s[tid] = b3[tid];
    if (tid < F2) { sc2[tid] = g_scale2[tid]; sh2[tid] = g_shift2[tid]; }
    {
        const float* yg = g_Y2 + (size_t)rowBase * F2;
        for (int i = tid; i < 128 * F2; i += 128) {
            int r = i / F2, c = i - r * F2;
            ys[r * 25 + c] = yg[i];
        }
    }
    __syncthreads();

    int row = rowBase + tid;
    float na = g_na2, nm = g_nm2;
    u32 ka = g_k2a, kb = g_k2b;
    u32 base = (u32)row * (u32)F2;

    float acc[F3];
#pragma unroll
    for (int j = 0; j < F3; j++) acc[j] = b3s[j];

#pragma unroll 4
    for (int c = 0; c < F2; c++) {
        float h = fmaf(ys[tid * 25 + c], sc2[c], sh2[c]);
        u32 o0, o1;
        tf2x32(ka, kb, 0u, base + (u32)c, o0, o1);
        float noi = fmaf(na, jax_normal(o0 ^ o1), nm);
        float zc = fmaxf(h + noi, 0.f);
#pragma unroll
        for (int j = 0; j < F3; j++)
            acc[j] = fmaf(zc, w3s[j * F2 + c], acc[j]);
    }

    __syncthreads();
#pragma unroll
    for (int j = 0; j < F3; j++) ys[tid * 11 + j] = acc[j];
    __syncthreads();
    {
        float* og = out + (size_t)rowBase * F3;
        for (int i = tid; i < 128 * F3; i += 128) {
            int r = i / F3, j = i - r * F3;
            og[i] = ys[r * 11 + j];
        }
    }
}

// ----------------------------- launch --------------------------------------
extern "C" void kernel_launch(void* const* d_in, const int* in_sizes, int n_in,
                              void* d_out, int out_size) {
    const float* x      = (const float*)d_in[0];
    const float* w1     = (const float*)d_in[1];
    const float* b1     = (const float*)d_in[2];
    const float* gamma1 = (const float*)d_in[3];
    const float* beta1  = (const float*)d_in[4];
    const float* w2     = (const float*)d_in[5];
    const float* b2     = (const float*)d_in[6];
    const float* gamma2 = (const float*)d_in[7];
    const float* beta2  = (const float*)d_in[8];
    const float* w3     = (const float*)d_in[9];
    const float* b3     = (const float*)d_in[10];
    float* out = (float*)d_out;

    k1_gemm<<<512, 128>>>(x, w1, b1);
    k2_fin<<<1, 512>>>(gamma1, beta1);
    k3_mid<<<512, 128>>>(w2, b2);
    k4_fin<<<1, 512>>>(gamma2, beta2);
    k5_out<<<512, 128>>>(w3, b3, out);
}

// round 6
// speedup vs baseline: 1.8639x; 1.8639x over previous
#include <cuda_runtime.h>
#include <cuda_bf16.h>
#include <cstddef>
#include <cstdint>

typedef unsigned int u32;
typedef unsigned long long ull;

#define NROWS 65536
#define F1 48
#define F2 24
#define F3 10
#define KDIM 784
#define EPSBN 1e-5f

// ----------------------------- device scratch -----------------------------
__device__ float g_Y1[(size_t)NROWS * F1];
__device__ float g_Y2[(size_t)NROWS * F2];
__device__ float g_p1s[512 * F1];
__device__ float g_p1q[512 * F1];
__device__ float g_p2s[512 * F2];
__device__ float g_p2q[512 * F2];
__device__ float g_scale1[F1], g_shift1[F1];
__device__ float g_scale2[F2], g_shift2[F2];
__device__ float g_na1, g_nm1, g_na2, g_nm2;
__device__ u32   g_k1a, g_k1b, g_k2a, g_k2b;

// ----------------------------- helpers ------------------------------------
__device__ __forceinline__ u32 smem_u32(const void* p) {
    u32 a;
    asm("{ .reg .u64 t; cvta.to.shared.u64 t, %1; cvt.u32.u64 %0, t; }"
        : "=r"(a) : "l"(p));
    return a;
}

// split fp32x4 -> hi/lo bf16x4 (each packed in one 8-byte word, k-ascending)
__device__ __forceinline__ void cvt_split(float4 v, ull &hi, ull &lo) {
    u32 h01, h23;
    asm("cvt.rn.bf16x2.f32 %0, %1, %2;" : "=r"(h01) : "f"(v.y), "f"(v.x));
    asm("cvt.rn.bf16x2.f32 %0, %1, %2;" : "=r"(h23) : "f"(v.w), "f"(v.z));
    float r0 = v.x - __uint_as_float(h01 << 16);
    float r1 = v.y - __uint_as_float(h01 & 0xFFFF0000u);
    float r2 = v.z - __uint_as_float(h23 << 16);
    float r3 = v.w - __uint_as_float(h23 & 0xFFFF0000u);
    u32 l01, l23;
    asm("cvt.rn.bf16x2.f32 %0, %1, %2;" : "=r"(l01) : "f"(r1), "f"(r0));
    asm("cvt.rn.bf16x2.f32 %0, %1, %2;" : "=r"(l23) : "f"(r3), "f"(r2));
    hi = ((ull)h23 << 32) | h01;
    lo = ((ull)l23 << 32) | l01;
}

#define LDMATRIX_X4(r, addr) \
    asm volatile("ldmatrix.sync.aligned.m8n8.x4.shared.b16 {%0,%1,%2,%3}, [%4];" \
        : "=r"((r)[0]), "=r"((r)[1]), "=r"((r)[2]), "=r"((r)[3]) : "r"(addr))

#define MMA_BF16(c, a, b0v, b1v) \
    asm volatile("mma.sync.aligned.m16n8k16.row.col.f32.bf16.bf16.f32 " \
        "{%0,%1,%2,%3}, {%4,%5,%6,%7}, {%8,%9}, {%0,%1,%2,%3};" \
        : "+f"((c)[0]), "+f"((c)[1]), "+f"((c)[2]), "+f"((c)[3]) \
        : "r"((a)[0]), "r"((a)[1]), "r"((a)[2]), "r"((a)[3]), \
          "r"(b0v), "r"(b1v))

#define LDS32(r, addr) \
    asm volatile("ld.shared.b32 %0, [%1];" : "=r"(r) : "r"(addr))

// ----------------------------- PRNG ----------------------------------------
__device__ __forceinline__ void tf2x32(u32 k0, u32 k1, u32 x0, u32 x1,
                                       u32 &o0, u32 &o1) {
    u32 k2 = k0 ^ k1 ^ 0x1BD11BDAu;
    x0 += k0; x1 += k1;
#define TF_R(r) { x0 += x1; x1 = __funnelshift_l(x1, x1, (r)); x1 ^= x0; }
    TF_R(13) TF_R(15) TF_R(26) TF_R(6)   x0 += k1; x1 += k2 + 1u;
    TF_R(17) TF_R(29) TF_R(16) TF_R(24)  x0 += k2; x1 += k0 + 2u;
    TF_R(13) TF_R(15) TF_R(26) TF_R(6)   x0 += k0; x1 += k1 + 3u;
    TF_R(17) TF_R(29) TF_R(16) TF_R(24)  x0 += k1; x1 += k2 + 4u;
    TF_R(13) TF_R(15) TF_R(26) TF_R(6)   x0 += k2; x1 += k0 + 5u;
#undef TF_R
    o0 = x0; o1 = x1;
}

__device__ __forceinline__ float jax_normal(u32 bits) {
    float u01 = __uint_as_float((bits >> 9) | 0x3f800000u) - 1.0f;
    float u   = fmaxf(-0.99999994f, fmaf(u01, 2.0f, -0.99999994f));
    float w   = -log1pf(-u * u);
    float p;
    if (w < 5.0f) {
        w -= 2.5f;
        p = 2.81022636e-08f;
        p = fmaf(p, w, 3.43273939e-07f);
        p = fmaf(p, w, -3.5233877e-06f);
        p = fmaf(p, w, -4.39150654e-06f);
        p = fmaf(p, w, 0.00021858087f);
        p = fmaf(p, w, -0.00125372503f);
        p = fmaf(p, w, -0.00417768164f);
        p = fmaf(p, w, 0.246640727f);
        p = fmaf(p, w, 1.50140941f);
    } else {
        w = sqrtf(w) - 3.0f;
        p = -0.000200214257f;
        p = fmaf(p, w, 0.000100950558f);
        p = fmaf(p, w, 0.00134934322f);
        p = fmaf(p, w, -0.00367342844f);
        p = fmaf(p, w, 0.00573950773f);
        p = fmaf(p, w, -0.0076224613f);
        p = fmaf(p, w, 0.00943887047f);
        p = fmaf(p, w, 1.00167406f);
        p = fmaf(p, w, 2.83297682f);
    }
    return 1.41421356f * (p * u);
}

// ----------------------------- K1: split-bf16 HMMA GEMM -------------------
// Y1 = x @ w1^T + b1.  CTA tile = 128 rows x 48 cols, K in 13 chunks of 64.
// D += Ahi*Bhi + Alo*Bhi + Ahi*Blo  (fp32 register accumulators).
#define KC1 64
#define NCHUNK 13
#define ASTRIDE 144          // bytes per smem row (64 bf16 padded to 72)

#define SM_AH  0
#define SM_AL  18432
#define SM_BH  36864
#define SM_BL  43776
#define SM_BIAS 50688
#define SM1_TOTAL 50944

__global__ void __launch_bounds__(128, 4) k1_mma(const float* __restrict__ x,
                                                 const float* __restrict__ w1,
                                                 const float* __restrict__ b1) {
    extern __shared__ char smem[];
    u32 sb = smem_u32(smem);
    int tid = threadIdx.x;
    int lane = tid & 31, wrp = tid >> 5;
    int rowBase = blockIdx.x * 128;

    if (tid < F1) ((float*)(smem + SM_BIAS))[tid] = b1[tid];

    // ldmatrix source addresses (per mtile), lane-dependent
    int mi  = lane >> 3;         // submatrix 0..3
    int rIn = lane & 7;
    u32 aoff[2];
#pragma unroll
    for (int mt = 0; mt < 2; mt++) {
        int row = wrp * 32 + mt * 16 + (mi & 1) * 8 + rIn;
        aoff[mt] = (u32)(row * ASTRIDE + (mi >> 1) * 16);
    }
    // B fragment base: row n = (lane>>2), k word = lane&3
    u32 boff = (u32)((lane >> 2) * ASTRIDE + (lane & 3) * 4);

    float C[2][6][4];
#pragma unroll
    for (int mt = 0; mt < 2; mt++)
#pragma unroll
        for (int nt = 0; nt < 6; nt++)
#pragma unroll
            for (int e = 0; e < 4; e++) C[mt][nt][e] = 0.f;

    const float4* x4 = (const float4*)x;
    const float4* w4 = (const float4*)w1;

    for (int c = 0; c < NCHUNK; c++) {
        int q0 = c * 16;                     // float4 column base (196 per row)
        // ---- load + split A tile: 128 rows x 64 floats ----
#pragma unroll
        for (int p = 0; p < 16; p++) {
            int e = p * 128 + tid;           // 0..2047
            int r = e >> 4, q = e & 15;
            float4 v = make_float4(0.f, 0.f, 0.f, 0.f);
            if (q0 + q < 196) v = x4[(size_t)(rowBase + r) * 196 + q0 + q];
            ull hi, lo; cvt_split(v, hi, lo);
            u32 off = (u32)(r * ASTRIDE + q * 8);
            *(ull*)(smem + SM_AH + off) = hi;
            *(ull*)(smem + SM_AL + off) = lo;
        }
        // ---- load + split B tile: 48 rows x 64 floats ----
#pragma unroll
        for (int p = 0; p < 6; p++) {
            int e = p * 128 + tid;           // 0..767
            int r = e >> 4, q = e & 15;
            float4 v = make_float4(0.f, 0.f, 0.f, 0.f);
            if (q0 + q < 196) v = w4[(size_t)r * 196 + q0 + q];
            ull hi, lo; cvt_split(v, hi, lo);
            u32 off = (u32)(r * ASTRIDE + q * 8);
            *(ull*)(smem + SM_BH + off) = hi;
            *(ull*)(smem + SM_BL + off) = lo;
        }
        __syncthreads();

        // ---- compute: 4 k-steps of 16 ----
#pragma unroll
        for (int ks = 0; ks < 4; ks++) {
            u32 kb = (u32)(ks * 32);
            u32 ah0[4], ah1[4], al0[4], al1[4];
            LDMATRIX_X4(ah0, sb + SM_AH + aoff[0] + kb);
            LDMATRIX_X4(ah1, sb + SM_AH + aoff[1] + kb);
            LDMATRIX_X4(al0, sb + SM_AL + aoff[0] + kb);
            LDMATRIX_X4(al1, sb + SM_AL + aoff[1] + kb);
#pragma unroll
            for (int nt = 0; nt < 6; nt++) {
                u32 ba = boff + (u32)(nt * 8 * ASTRIDE) + kb;
                u32 bh0, bh1, bl0, bl1;
                LDS32(bh0, sb + SM_BH + ba);
                LDS32(bh1, sb + SM_BH + ba + 16);
                LDS32(bl0, sb + SM_BL + ba);
                LDS32(bl1, sb + SM_BL + ba + 16);
                MMA_BF16(C[0][nt], ah0, bh0, bh1);
                MMA_BF16(C[1][nt], ah1, bh0, bh1);
                MMA_BF16(C[0][nt], al0, bh0, bh1);
                MMA_BF16(C[1][nt], al1, bh0, bh1);
                MMA_BF16(C[0][nt], ah0, bl0, bl1);
                MMA_BF16(C[1][nt], ah1, bl0, bl1);
            }
        }
        __syncthreads();
    }

    // ---- epilogue: bias, stage to smem, stats, coalesced write ----
    float* ys = (float*)(smem + SM_AH);      // 128 x 49 fp32 = 25088 B
    const float* bs = (const float*)(smem + SM_BIAS);
    int rg = lane >> 2, cg = (lane & 3) * 2;
#pragma unroll
    for (int mt = 0; mt < 2; mt++) {
        int r0 = wrp * 32 + mt * 16 + rg;
#pragma unroll
        for (int nt = 0; nt < 6; nt++) {
            int col = nt * 8 + cg;
            ys[r0 * 49 + col]           = C[mt][nt][0] + bs[col];
            ys[r0 * 49 + col + 1]       = C[mt][nt][1] + bs[col + 1];
            ys[(r0 + 8) * 49 + col]     = C[mt][nt][2] + bs[col];
            ys[(r0 + 8) * 49 + col + 1] = C[mt][nt][3] + bs[col + 1];
        }
    }
    __syncthreads();

    if (tid < F1) {
        float s = 0.f, q = 0.f;
        for (int r = 0; r < 128; r++) {
            float v = ys[r * 49 + tid];
            s += v; q += v * v;
        }
        g_p1s[blockIdx.x * F1 + tid] = s;
        g_p1q[blockIdx.x * F1 + tid] = q;
    }
    float* yg = g_Y1 + (size_t)rowBase * F1;
#pragma unroll 4
    for (int p = 0; p < 48; p++) {
        int i = p * 128 + tid;               // 0..6143
        int r = i / F1, cc = i - r * F1;
        yg[i] = ys[r * 49 + cc];
    }
}

// ----------------------------- K2: finalize layer-1 stats -----------------
__global__ void __launch_bounds__(1024) k2_fin(const float* __restrict__ gamma,
                                               const float* __restrict__ beta) {
    __shared__ float smS[21 * F1], smQ[21 * F1];
    __shared__ float term[F1], betas[F1];
    int tid = threadIdx.x;
    int col = tid % F1, g = tid / F1;
    if (tid < 21 * F1) {
        float s = 0.f, q = 0.f;
        for (int b = g; b < 512; b += 21) {
            s += g_p1s[b * F1 + col];
            q += g_p1q[b * F1 + col];
        }
        smS[g * F1 + col] = s;
        smQ[g * F1 + col] = q;
    }
    __syncthreads();
    if (tid < F1) {
        float ss = 0.f, qq = 0.f;
        for (int g2 = 0; g2 < 21; g2++) {
            ss += smS[g2 * F1 + tid];
            qq += smQ[g2 * F1 + tid];
        }
        float m = ss / 65536.0f;
        float v = fmaxf(qq / 65536.0f - m * m, 0.f);
        float ga = gamma[tid], be = beta[tid];
        float sc = ga * rsqrtf(v + EPSBN);
        g_scale1[tid] = sc;
        g_shift1[tid] = be - m * sc;
        betas[tid] = be;
        term[tid]  = ga * ga * (v / (v + EPSBN));
    }
    __syncthreads();
    if (tid == 0) {
        float nb = 0.f;
        for (int c = 0; c < F1; c++) nb += betas[c];
        float nm = nb / (float)F1;
        float S = 0.f;
        for (int c = 0; c < F1; c++) {
            float d = betas[c] - nm;
            S += term[c] + d * d;
        }
        float var = (65536.0f * S) / (65536.0f * (float)F1 - 1.0f);
        float sdev = sqrtf(var);
        u32 ka, kb, na, nbk;
        tf2x32(0u, 1234u, 0u, 0u, ka, kb);
        tf2x32(0u, 1234u, 0u, 1u, na, nbk);
        u32 u0, u1;
        tf2x32(ka, kb, 0u, 0u, u0, u1);
        u32 bits = u0 ^ u1;
        float u01 = __uint_as_float((bits >> 9) | 0x3f800000u) - 1.0f;
        float uu = fmaxf(1.0f, u01 + 1.0f);
        g_na1 = sdev * uu;
        g_nm1 = nm;
        g_k1a = na; g_k1b = nbk;
    }
}

// ----------------------------- K3: BN1+noise+ReLU -> GEMM2 ----------------
__global__ void __launch_bounds__(128) k3_mid(const float* __restrict__ w2,
                                              const float* __restrict__ b2) {
    __shared__ float ys[128 * 49];
    __shared__ float w2s[F2 * F1];
    __shared__ float b2s[F2];
    __shared__ float sc1[F1], sh1[F1];
    __shared__ float wrs[4 * F2], wrq[4 * F2];
    int tid = threadIdx.x;
    int rowBase = blockIdx.x * 128;

    for (int i = tid; i < F2 * F1; i += 128) w2s[i] = w2[i];
    if (tid < F2) b2s[tid] = b2[tid];
    if (tid < F1) { sc1[tid] = g_scale1[tid]; sh1[tid] = g_shift1[tid]; }
    {
        const float* yg = g_Y1 + (size_t)rowBase * F1;
        for (int i = tid; i < 128 * F1; i += 128) {
            int r = i / F1, c = i - r * F1;
            ys[r * 49 + c] = yg[i];
        }
    }
    __syncthreads();

    float na = g_na1, nm = g_nm1;
    u32 ka = g_k1a, kb = g_k1b;
    u32 base = (u32)(rowBase + tid) * (u32)F1;

    float acc[F2];
#pragma unroll
    for (int j = 0; j < F2; j++) acc[j] = b2s[j];

#pragma unroll 4
    for (int c = 0; c < F1; c++) {
        float h = fmaf(ys[tid * 49 + c], sc1[c], sh1[c]);
        u32 o0, o1;
        tf2x32(ka, kb, 0u, base + (u32)c, o0, o1);
        float noi = fmaf(na, jax_normal(o0 ^ o1), nm);
        float zc = fmaxf(h + noi, 0.f);
#pragma unroll
        for (int j = 0; j < F2; j++)
            acc[j] = fmaf(zc, w2s[j * F1 + c], acc[j]);
    }

    int lane = tid & 31, wrp = tid >> 5;
#pragma unroll
    for (int j = 0; j < F2; j++) {
        float sv = acc[j], qv = acc[j] * acc[j];
#pragma unroll
        for (int off = 16; off > 0; off >>= 1) {
            sv += __shfl_down_sync(0xffffffffu, sv, off);
            qv += __shfl_down_sync(0xffffffffu, qv, off);
        }
        if (lane == 0) { wrs[wrp * F2 + j] = sv; wrq[wrp * F2 + j] = qv; }
    }

    __syncthreads();
    if (tid < F2) {
        g_p2s[blockIdx.x * F2 + tid] =
            wrs[tid] + wrs[F2 + tid] + wrs[2 * F2 + tid] + wrs[3 * F2 + tid];
        g_p2q[blockIdx.x * F2 + tid] =
            wrq[tid] + wrq[F2 + tid] + wrq[2 * F2 + tid] + wrq[3 * F2 + tid];
    }

#pragma unroll
    for (int j = 0; j < F2; j++) ys[tid * 25 + j] = acc[j];
    __syncthreads();
    {
        float* yg2 = g_Y2 + (size_t)rowBase * F2;
        for (int i = tid; i < 128 * F2; i += 128) {
            int r = i / F2, j = i - r * F2;
            yg2[i] = ys[r * 25 + j];
        }
    }
}

// ----------------------------- K4: finalize layer-2 stats -----------------
__global__ void __launch_bounds__(1024) k4_fin(const float* __restrict__ gamma,
                                               const float* __restrict__ beta) {
    __shared__ float smS[42 * F2], smQ[42 * F2];
    __shared__ float term[F2], betas[F2];
    int tid = threadIdx.x;
    int col = tid % F2, g = tid / F2;
    if (tid < 42 * F2) {
        float s = 0.f, q = 0.f;
        for (int b = g; b < 512; b += 42) {
            s += g_p2s[b * F2 + col];
            q += g_p2q[b * F2 + col];
        }
        smS[g * F2 + col] = s;
        smQ[g * F2 + col] = q;
    }
    __syncthreads();
    if (tid < F2) {
        float ss = 0.f, qq = 0.f;
        for (int g2 = 0; g2 < 42; g2++) {
            ss += smS[g2 * F2 + tid];
            qq += smQ[g2 * F2 + tid];
        }
        float m = ss / 65536.0f;
        float v = fmaxf(qq / 65536.0f - m * m, 0.f);
        float ga = gamma[tid], be = beta[tid];
        float sc = ga * rsqrtf(v + EPSBN);
        g_scale2[tid] = sc;
        g_shift2[tid] = be - m * sc;
        betas[tid] = be;
        term[tid]  = ga * ga * (v / (v + EPSBN));
    }
    __syncthreads();
    if (tid == 0) {
        float nb = 0.f;
        for (int c = 0; c < F2; c++) nb += betas[c];
        float nm = nb / (float)F2;
        float S = 0.f;
        for (int c = 0; c < F2; c++) {
            float d = betas[c] - nm;
            S += term[c] + d * d;
        }
        float var = (65536.0f * S) / (65536.0f * (float)F2 - 1.0f);
        float sdev = sqrtf(var);
        u32 ka, kb, na, nbk;
        tf2x32(0u, 5678u, 0u, 0u, ka, kb);
        tf2x32(0u, 5678u, 0u, 1u, na, nbk);
        u32 u0, u1;
        tf2x32(ka, kb, 0u, 0u, u0, u1);
        u32 bits = u0 ^ u1;
        float u01 = __uint_as_float((bits >> 9) | 0x3f800000u) - 1.0f;
        float uu = fmaxf(1.0f, u01 + 1.0f);
        g_na2 = sdev * uu;
        g_nm2 = nm;
        g_k2a = na; g_k2b = nbk;
    }
}

// ----------------------------- K5: BN2+noise+ReLU -> GEMM3 -> out ---------
__global__ void __launch_bounds__(128) k5_out(const float* __restrict__ w3,
                                              const float* __restrict__ b3,
                                              float* __restrict__ out) {
    __shared__ float ys[128 * 25];
    __shared__ float w3s[F3 * F2];
    __shared__ float b3s[F3];
    __shared__ float sc2[F2], sh2[F2];
    int tid = threadIdx.x;
    int rowBase = blockIdx.x * 128;

    for (int i = tid; i < F3 * F2; i += 128) w3s[i] = w3[i];
    if (tid < F3) b3s[tid] = b3[tid];
    if (tid < F2) { sc2[tid] = g_scale2[tid]; sh2[tid] = g_shift2[tid]; }
    {
        const float* yg = g_Y2 + (size_t)rowBase * F2;
        for (int i = tid; i < 128 * F2; i += 128) {
            int r = i / F2, c = i - r * F2;
            ys[r * 25 + c] = yg[i];
        }
    }
    __syncthreads();

    float na = g_na2, nm = g_nm2;
    u32 ka = g_k2a, kb = g_k2b;
    u32 base = (u32)(rowBase + tid) * (u32)F2;

    float acc[F3];
#pragma unroll
    for (int j = 0; j < F3; j++) acc[j] = b3s[j];

#pragma unroll 4
    for (int c = 0; c < F2; c++) {
        float h = fmaf(ys[tid * 25 + c], sc2[c], sh2[c]);
        u32 o0, o1;
        tf2x32(ka, kb, 0u, base + (u32)c, o0, o1);
        float noi = fmaf(na, jax_normal(o0 ^ o1), nm);
        float zc = fmaxf(h + noi, 0.f);
#pragma unroll
        for (int j = 0; j < F3; j++)
            acc[j] = fmaf(zc, w3s[j * F2 + c], acc[j]);
    }

    __syncthreads();
#pragma unroll
    for (int j = 0; j < F3; j++) ys[tid * 11 + j] = acc[j];
    __syncthreads();
    {
        float* og = out + (size_t)rowBase * F3;
        for (int i = tid; i < 128 * F3; i += 128) {
            int r = i / F3, j = i - r * F3;
            og[i] = ys[r * 11 + j];
        }
    }
}

// ----------------------------- launch --------------------------------------
extern "C" void kernel_launch(void* const* d_in, const int* in_sizes, int n_in,
                              void* d_out, int out_size) {
    const float* x      = (const float*)d_in[0];
    const float* w1     = (const float*)d_in[1];
    const float* b1     = (const float*)d_in[2];
    const float* gamma1 = (const float*)d_in[3];
    const float* beta1  = (const float*)d_in[4];
    const float* w2     = (const float*)d_in[5];
    const float* b2     = (const float*)d_in[6];
    const float* gamma2 = (const float*)d_in[7];
    const float* beta2  = (const float*)d_in[8];
    const float* w3     = (const float*)d_in[9];
    const float* b3     = (const float*)d_in[10];
    float* out = (float*)d_out;

    cudaFuncSetAttribute(k1_mma, cudaFuncAttributeMaxDynamicSharedMemorySize,
                         SM1_TOTAL);

    k1_mma<<<512, 128, SM1_TOTAL>>>(x, w1, b1);
    k2_fin<<<1, 1024>>>(gamma1, beta1);
    k3_mid<<<512, 128>>>(w2, b2);
    k4_fin<<<1, 1024>>>(gamma2, beta2);
    k5_out<<<512, 128>>>(w3, b3, out);
}

// round 7
// speedup vs baseline: 1.9395x; 1.0406x over previous
#include <cuda_runtime.h>
#include <cuda_fp16.h>
#include <cstddef>
#include <cstdint>

typedef unsigned int u32;
typedef unsigned long long ull;

#define NROWS 65536
#define F1 48
#define F2 24
#define F3 10
#define KDIM 784
#define EPSBN 1e-5f

// ----------------------------- device scratch -----------------------------
__device__ float g_Y1[(size_t)NROWS * F1];
__device__ float g_Y2[(size_t)NROWS * F2];
__device__ float g_p1s[F1 * 512];
__device__ float g_p1q[F1 * 512];
__device__ float g_p2s[F2 * 512];
__device__ float g_p2q[F2 * 512];
__device__ float g_scale1[F1], g_shift1[F1];
__device__ float g_scale2[F2], g_shift2[F2];
__device__ float g_na1, g_nm1, g_na2, g_nm2;
__device__ u32   g_k1a, g_k1b, g_k2a, g_k2b;
__device__ u32   g_cnt1 = 0, g_cnt2 = 0;

// ----------------------------- helpers ------------------------------------
__device__ __forceinline__ u32 smem_u32(const void* p) {
    u32 a;
    asm("{ .reg .u64 t; cvta.to.shared.u64 t, %1; cvt.u32.u64 %0, t; }"
        : "=r"(a) : "l"(p));
    return a;
}

// round fp32x4 -> fp16x4 (one 8-byte word, k-ascending)
__device__ __forceinline__ ull cvt_hi_h(float4 v) {
    u32 h01, h23;
    asm("cvt.rn.f16x2.f32 %0, %1, %2;" : "=r"(h01) : "f"(v.y), "f"(v.x));
    asm("cvt.rn.f16x2.f32 %0, %1, %2;" : "=r"(h23) : "f"(v.w), "f"(v.z));
    return ((ull)h23 << 32) | h01;
}

// split fp32x4 -> hi/lo fp16x4
__device__ __forceinline__ void cvt_split_h(float4 v, ull &hi, ull &lo) {
    u32 h01, h23;
    asm("cvt.rn.f16x2.f32 %0, %1, %2;" : "=r"(h01) : "f"(v.y), "f"(v.x));
    asm("cvt.rn.f16x2.f32 %0, %1, %2;" : "=r"(h23) : "f"(v.w), "f"(v.z));
    float f0, f1, f2, f3;
    asm("{.reg .f16 a,b; mov.b32 {a,b}, %2; cvt.f32.f16 %0, a; cvt.f32.f16 %1, b;}"
        : "=f"(f0), "=f"(f1) : "r"(h01));
    asm("{.reg .f16 a,b; mov.b32 {a,b}, %2; cvt.f32.f16 %0, a; cvt.f32.f16 %1, b;}"
        : "=f"(f2), "=f"(f3) : "r"(h23));
    float r0 = v.x - f0, r1 = v.y - f1, r2 = v.z - f2, r3 = v.w - f3;
    u32 l01, l23;
    asm("cvt.rn.f16x2.f32 %0, %1, %2;" : "=r"(l01) : "f"(r1), "f"(r0));
    asm("cvt.rn.f16x2.f32 %0, %1, %2;" : "=r"(l23) : "f"(r3), "f"(r2));
    hi = ((ull)h23 << 32) | h01;
    lo = ((ull)l23 << 32) | l01;
}

#define LDMATRIX_X4(r, addr) \
    asm volatile("ldmatrix.sync.aligned.m8n8.x4.shared.b16 {%0,%1,%2,%3}, [%4];" \
        : "=r"((r)[0]), "=r"((r)[1]), "=r"((r)[2]), "=r"((r)[3]) : "r"(addr))

#define MMA_F16(c, a, b0v, b1v) \
    asm volatile("mma.sync.aligned.m16n8k16.row.col.f32.f16.f16.f32 " \
        "{%0,%1,%2,%3}, {%4,%5,%6,%7}, {%8,%9}, {%0,%1,%2,%3};" \
        : "+f"((c)[0]), "+f"((c)[1]), "+f"((c)[2]), "+f"((c)[3]) \
        : "r"((a)[0]), "r"((a)[1]), "r"((a)[2]), "r"((a)[3]), \
          "r"(b0v), "r"(b1v))

#define LDS32(r, addr) \
    asm volatile("ld.shared.b32 %0, [%1];" : "=r"(r) : "r"(addr))

// ----------------------------- PRNG ----------------------------------------
__device__ __forceinline__ void tf2x32(u32 k0, u32 k1, u32 x0, u32 x1,
                                       u32 &o0, u32 &o1) {
    u32 k2 = k0 ^ k1 ^ 0x1BD11BDAu;
    x0 += k0; x1 += k1;
#define TF_R(r) { x0 += x1; x1 = __funnelshift_l(x1, x1, (r)); x1 ^= x0; }
    TF_R(13) TF_R(15) TF_R(26) TF_R(6)   x0 += k1; x1 += k2 + 1u;
    TF_R(17) TF_R(29) TF_R(16) TF_R(24)  x0 += k2; x1 += k0 + 2u;
    TF_R(13) TF_R(15) TF_R(26) TF_R(6)   x0 += k0; x1 += k1 + 3u;
    TF_R(17) TF_R(29) TF_R(16) TF_R(24)  x0 += k1; x1 += k2 + 4u;
    TF_R(13) TF_R(15) TF_R(26) TF_R(6)   x0 += k2; x1 += k0 + 5u;
#undef TF_R
    o0 = x0; o1 = x1;
}

__device__ __forceinline__ float jax_normal(u32 bits) {
    float u01 = __uint_as_float((bits >> 9) | 0x3f800000u) - 1.0f;
    float u   = fmaxf(-0.99999994f, fmaf(u01, 2.0f, -0.99999994f));
    float w   = -log1pf(-u * u);
    float p;
    if (w < 5.0f) {
        w -= 2.5f;
        p = 2.81022636e-08f;
        p = fmaf(p, w, 3.43273939e-07f);
        p = fmaf(p, w, -3.5233877e-06f);
        p = fmaf(p, w, -4.39150654e-06f);
        p = fmaf(p, w, 0.00021858087f);
        p = fmaf(p, w, -0.00125372503f);
        p = fmaf(p, w, -0.00417768164f);
        p = fmaf(p, w, 0.246640727f);
        p = fmaf(p, w, 1.50140941f);
    } else {
        w = sqrtf(w) - 3.0f;
        p = -0.000200214257f;
        p = fmaf(p, w, 0.000100950558f);
        p = fmaf(p, w, 0.00134934322f);
        p = fmaf(p, w, -0.00367342844f);
        p = fmaf(p, w, 0.00573950773f);
        p = fmaf(p, w, -0.0076224613f);
        p = fmaf(p, w, 0.00943887047f);
        p = fmaf(p, w, 1.00167406f);
        p = fmaf(p, w, 2.83297682f);
    }
    return 1.41421356f * (p * u);
}

// ----------------------------- K1: fp16 2-pass HMMA GEMM + fin1 -----------
// Y1 = x @ w1^T + b1.  CTA tile = 128 rows x 48 cols, K in 13 chunks of 64.
// D = Xh * (Whi + Wlo)  (x rounded to fp16, w split hi/lo fp16).
#define NCHUNK 13
#define BSTR 144          // smem row stride (64 fp16 = 128B data + 16B pad)

#define SM_AH   0         // 128 x 144 = 18432
#define SM_BH   18432     // 48 x 144  = 6912
#define SM_BL   25344     // 6912
#define SM_BIAS 32256     // 192
#define SM1_TOTAL 32448

__global__ void __launch_bounds__(128, 5) k1_mma(const float* __restrict__ x,
                                                 const float* __restrict__ w1,
                                                 const float* __restrict__ b1,
                                                 const float* __restrict__ gamma,
                                                 const float* __restrict__ beta) {
    extern __shared__ char smem[];
    u32 sb = smem_u32(smem);
    int tid = threadIdx.x;
    int lane = tid & 31, wrp = tid >> 5;
    int rowBase = blockIdx.x * 128;

    if (tid < F1) ((float*)(smem + SM_BIAS))[tid] = b1[tid];

    // ldmatrix source addresses for A (per m-tile)
    int mi  = lane >> 3;
    int rIn = lane & 7;
    u32 aoff[2];
#pragma unroll
    for (int mt = 0; mt < 2; mt++) {
        int row = wrp * 32 + mt * 16 + (mi & 1) * 8 + rIn;
        aoff[mt] = (u32)(row * BSTR + (mi >> 1) * 16);
    }
    u32 boff = (u32)((lane >> 2) * BSTR + (lane & 3) * 4);

    float C[2][6][4];
#pragma unroll
    for (int mt = 0; mt < 2; mt++)
#pragma unroll
        for (int nt = 0; nt < 6; nt++)
#pragma unroll
            for (int e = 0; e < 4; e++) C[mt][nt][e] = 0.f;

    const float4* x4 = (const float4*)x;
    const float4* w4 = (const float4*)w1;

#pragma unroll 1
    for (int c = 0; c < NCHUNK; c++) {
        int q0 = c * 16;                     // float4 column base (196/row)
        // A tile: 128 rows x 64 floats -> fp16 (single)
#pragma unroll
        for (int p = 0; p < 16; p++) {
            int e = p * 128 + tid;
            int r = e >> 4, q = e & 15;
            float4 v = make_float4(0.f, 0.f, 0.f, 0.f);
            if (q0 + q < 196) v = x4[(size_t)(rowBase + r) * 196 + q0 + q];
            *(ull*)(smem + SM_AH + r * BSTR + q * 8) = cvt_hi_h(v);
        }
        // B tile: 48 rows x 64 floats -> fp16 hi + lo
#pragma unroll
        for (int p = 0; p < 6; p++) {
            int e = p * 128 + tid;
            int r = e >> 4, q = e & 15;
            float4 v = make_float4(0.f, 0.f, 0.f, 0.f);
            if (q0 + q < 196) v = w4[(size_t)r * 196 + q0 + q];
            ull hi, lo; cvt_split_h(v, hi, lo);
            *(ull*)(smem + SM_BH + r * BSTR + q * 8) = hi;
            *(ull*)(smem + SM_BL + r * BSTR + q * 8) = lo;
        }
        __syncthreads();

#pragma unroll
        for (int ks = 0; ks < 4; ks++) {
            u32 kb = (u32)(ks * 32);
            u32 ah0[4], ah1[4];
            LDMATRIX_X4(ah0, sb + SM_AH + aoff[0] + kb);
            LDMATRIX_X4(ah1, sb + SM_AH + aoff[1] + kb);
#pragma unroll
            for (int nt = 0; nt < 6; nt++) {
                u32 ba = boff + (u32)(nt * 8 * BSTR) + kb;
                u32 bh0, bh1, bl0, bl1;
                LDS32(bh0, sb + SM_BH + ba);
                LDS32(bh1, sb + SM_BH + ba + 16);
                LDS32(bl0, sb + SM_BL + ba);
                LDS32(bl1, sb + SM_BL + ba + 16);
                MMA_F16(C[0][nt], ah0, bh0, bh1);
                MMA_F16(C[1][nt], ah1, bh0, bh1);
                MMA_F16(C[0][nt], ah0, bl0, bl1);
                MMA_F16(C[1][nt], ah1, bl0, bl1);
            }
        }
        __syncthreads();
    }

    // ---- epilogue: bias, stage, stats, coalesced write ----
    float* ys = (float*)(smem + SM_AH);      // 128 x 49 fp32 = 25088 B
    const float* bs = (const float*)(smem + SM_BIAS);
    int rg = lane >> 2, cg = (lane & 3) * 2;
#pragma unroll
    for (int mt = 0; mt < 2; mt++) {
        int r0 = wrp * 32 + mt * 16 + rg;
#pragma unroll
        for (int nt = 0; nt < 6; nt++) {
            int col = nt * 8 + cg;
            ys[r0 * 49 + col]           = C[mt][nt][0] + bs[col];
            ys[r0 * 49 + col + 1]       = C[mt][nt][1] + bs[col + 1];
            ys[(r0 + 8) * 49 + col]     = C[mt][nt][2] + bs[col];
            ys[(r0 + 8) * 49 + col + 1] = C[mt][nt][3] + bs[col + 1];
        }
    }
    __syncthreads();

    if (tid < F1) {                          // transposed partials [col][block]
        float s = 0.f, q = 0.f;
        for (int r = 0; r < 128; r++) {
            float v = ys[r * 49 + tid];
            s += v; q += v * v;
        }
        g_p1s[tid * 512 + blockIdx.x] = s;
        g_p1q[tid * 512 + blockIdx.x] = q;
    }
    float* yg = g_Y1 + (size_t)rowBase * F1;
#pragma unroll 4
    for (int p = 0; p < 48; p++) {
        int i = p * 128 + tid;
        int r = i / F1, cc = i - r * F1;
        yg[i] = ys[r * 49 + cc];
    }

    // ---- last-block finalize (replaces k2_fin) ----
    __shared__ u32 fin_last;
    __shared__ float fin_term[F1], fin_beta[F1];
    __threadfence();
    __syncthreads();
    if (tid == 0) fin_last = (atomicAdd(&g_cnt1, 1u) == 511u) ? 1u : 0u;
    __syncthreads();
    if (fin_last == 0u) return;
    __threadfence();

    if (tid < F1) {
        const float4* ps = (const float4*)(g_p1s + (size_t)tid * 512);
        const float4* pq = (const float4*)(g_p1q + (size_t)tid * 512);
        float s = 0.f, q = 0.f;
#pragma unroll 8
        for (int i = 0; i < 128; i++) {
            float4 a = ps[i]; s += (a.x + a.y) + (a.z + a.w);
            float4 b = pq[i]; q += (b.x + b.y) + (b.z + b.w);
        }
        float m = s / 65536.0f;
        float v = fmaxf(q / 65536.0f - m * m, 0.f);
        float ga = gamma[tid], be = beta[tid];
        float sc = ga * rsqrtf(v + EPSBN);
        g_scale1[tid] = sc;
        g_shift1[tid] = be - m * sc;
        fin_beta[tid] = be;
        fin_term[tid] = ga * ga * (v / (v + EPSBN));
    }
    __syncthreads();
    if (tid == 0) {
        float nb = 0.f;
        for (int c = 0; c < F1; c++) nb += fin_beta[c];
        float nm = nb / (float)F1;
        float S = 0.f;
        for (int c = 0; c < F1; c++) {
            float d = fin_beta[c] - nm;
            S += fin_term[c] + d * d;
        }
        float var = (65536.0f * S) / (65536.0f * (float)F1 - 1.0f);
        float sdev = sqrtf(var);
        u32 ka, kb2, na, nbk;
        tf2x32(0u, 1234u, 0u, 0u, ka, kb2);
        tf2x32(0u, 1234u, 0u, 1u, na, nbk);
        u32 u0, u1;
        tf2x32(ka, kb2, 0u, 0u, u0, u1);
        u32 bits = u0 ^ u1;
        float u01 = __uint_as_float((bits >> 9) | 0x3f800000u) - 1.0f;
        float uu = fmaxf(1.0f, u01 + 1.0f);
        g_na1 = sdev * uu;
        g_nm1 = nm;
        g_k1a = na; g_k1b = nbk;
        g_cnt1 = 0u;
    }
}

// ----------------------------- K3: BN1+noise+ReLU -> GEMM2 + fin2 ---------
__global__ void __launch_bounds__(128) k3_mid(const float* __restrict__ w2,
                                              const float* __restrict__ b2,
                                              const float* __restrict__ gamma,
                                              const float* __restrict__ beta) {
    __shared__ float ys[128 * 49];
    __shared__ float w2s[F2 * F1];
    __shared__ float b2s[F2];
    __shared__ float sc1[F1], sh1[F1];
    __shared__ float wrs[4 * F2], wrq[4 * F2];
    int tid = threadIdx.x;
    int rowBase = blockIdx.x * 128;

    for (int i = tid; i < F2 * F1; i += 128) w2s[i] = w2[i];
    if (tid < F2) b2s[tid] = b2[tid];
    if (tid < F1) { sc1[tid] = g_scale1[tid]; sh1[tid] = g_shift1[tid]; }
    {
        const float* yg = g_Y1 + (size_t)rowBase * F1;
        for (int i = tid; i < 128 * F1; i += 128) {
            int r = i / F1, c = i - r * F1;
            ys[r * 49 + c] = yg[i];
        }
    }
    __syncthreads();

    float na = g_na1, nm = g_nm1;
    u32 ka = g_k1a, kb = g_k1b;
    u32 base = (u32)(rowBase + tid) * (u32)F1;

    float acc[F2];
#pragma unroll
    for (int j = 0; j < F2; j++) acc[j] = b2s[j];

#pragma unroll 4
    for (int c = 0; c < F1; c++) {
        float h = fmaf(ys[tid * 49 + c], sc1[c], sh1[c]);
        u32 o0, o1;
        tf2x32(ka, kb, 0u, base + (u32)c, o0, o1);
        float noi = fmaf(na, jax_normal(o0 ^ o1), nm);
        float zc = fmaxf(h + noi, 0.f);
#pragma unroll
        for (int j = 0; j < F2; j++)
            acc[j] = fmaf(zc, w2s[j * F1 + c], acc[j]);
    }

    int lane = tid & 31, wrp = tid >> 5;
#pragma unroll
    for (int j = 0; j < F2; j++) {
        float sv = acc[j], qv = acc[j] * acc[j];
#pragma unroll
        for (int off = 16; off > 0; off >>= 1) {
            sv += __shfl_down_sync(0xffffffffu, sv, off);
            qv += __shfl_down_sync(0xffffffffu, qv, off);
        }
        if (lane == 0) { wrs[wrp * F2 + j] = sv; wrq[wrp * F2 + j] = qv; }
    }

    __syncthreads();
    if (tid < F2) {                          // transposed partials [col][block]
        g_p2s[tid * 512 + blockIdx.x] =
            wrs[tid] + wrs[F2 + tid] + wrs[2 * F2 + tid] + wrs[3 * F2 + tid];
        g_p2q[tid * 512 + blockIdx.x] =
            wrq[tid] + wrq[F2 + tid] + wrq[2 * F2 + tid] + wrq[3 * F2 + tid];
    }

#pragma unroll
    for (int j = 0; j < F2; j++) ys[tid * 25 + j] = acc[j];
    __syncthreads();
    {
        float* yg2 = g_Y2 + (size_t)rowBase * F2;
        for (int i = tid; i < 128 * F2; i += 128) {
            int r = i / F2, j = i - r * F2;
            yg2[i] = ys[r * 25 + j];
        }
    }

    // ---- last-block finalize (replaces k4_fin) ----
    __shared__ u32 fin_last;
    __shared__ float fin_term[F2], fin_beta[F2];
    __threadfence();
    __syncthreads();
    if (tid == 0) fin_last = (atomicAdd(&g_cnt2, 1u) == 511u) ? 1u : 0u;
    __syncthreads();
    if (fin_last == 0u) return;
    __threadfence();

    if (tid < F2) {
        const float4* ps = (const float4*)(g_p2s + (size_t)tid * 512);
        const float4* pq = (const float4*)(g_p2q + (size_t)tid * 512);
        float s = 0.f, q = 0.f;
#pragma unroll 8
        for (int i = 0; i < 128; i++) {
            float4 a = ps[i]; s += (a.x + a.y) + (a.z + a.w);
            float4 b = pq[i]; q += (b.x + b.y) + (b.z + b.w);
        }
        float m = s / 65536.0f;
        float v = fmaxf(q / 65536.0f - m * m, 0.f);
        float ga = gamma[tid], be = beta[tid];
        float sc = ga * rsqrtf(v + EPSBN);
        g_scale2[tid] = sc;
        g_shift2[tid] = be - m * sc;
        fin_beta[tid] = be;
        fin_term[tid] = ga * ga * (v / (v + EPSBN));
    }
    __syncthreads();
    if (tid == 0) {
        float nb = 0.f;
        for (int c = 0; c < F2; c++) nb += fin_beta[c];
        float nm2 = nb / (float)F2;
        float S = 0.f;
        for (int c = 0; c < F2; c++) {
            float d = fin_beta[c] - nm2;
            S += fin_term[c] + d * d;
        }
        float var = (65536.0f * S) / (65536.0f * (float)F2 - 1.0f);
        float sdev = sqrtf(var);
        u32 ka2, kb2, na2, nbk2;
        tf2x32(0u, 5678u, 0u, 0u, ka2, kb2);
        tf2x32(0u, 5678u, 0u, 1u, na2, nbk2);
        u32 u0, u1;
        tf2x32(ka2, kb2, 0u, 0u, u0, u1);
        u32 bits = u0 ^ u1;
        float u01 = __uint_as_float((bits >> 9) | 0x3f800000u) - 1.0f;
        float uu = fmaxf(1.0f, u01 + 1.0f);
        g_na2 = sdev * uu;
        g_nm2 = nm2;
        g_k2a = na2; g_k2b = nbk2;
        g_cnt2 = 0u;
    }
}

// ----------------------------- K5: BN2+noise+ReLU -> GEMM3 -> out ---------
__global__ void __launch_bounds__(128) k5_out(const float* __restrict__ w3,
                                              const float* __restrict__ b3,
                                              float* __restrict__ out) {
    __shared__ float ys[128 * 25];
    __shared__ float w3s[F3 * F2];
    __shared__ float b3s[F3];
    __shared__ float sc2[F2], sh2[F2];
    int tid = threadIdx.x;
    int rowBase = blockIdx.x * 128;

    for (int i = tid; i < F3 * F2; i += 128) w3s[i] = w3[i];
    if (tid < F3) b3s[tid] = b3[tid];
    if (tid < F2) { sc2[tid] = g_scale2[tid]; sh2[tid] = g_shift2[tid]; }
    {
        const float* yg = g_Y2 + (size_t)rowBase * F2;
        for (int i = tid; i < 128 * F2; i += 128) {
            int r = i / F2, c = i - r * F2;
            ys[r * 25 + c] = yg[i];
        }
    }
    __syncthreads();

    float na = g_na2, nm = g_nm2;
    u32 ka = g_k2a, kb = g_k2b;
    u32 base = (u32)(rowBase + tid) * (u32)F2;

    float acc[F3];
#pragma unroll
    for (int j = 0; j < F3; j++) acc[j] = b3s[j];

#pragma unroll 4
    for (int c = 0; c < F2; c++) {
        float h = fmaf(ys[tid * 25 + c], sc2[c], sh2[c]);
        u32 o0, o1;
        tf2x32(ka, kb, 0u, base + (u32)c, o0, o1);
        float noi = fmaf(na, jax_normal(o0 ^ o1), nm);
        float zc = fmaxf(h + noi, 0.f);
#pragma unroll
        for (int j = 0; j < F3; j++)
            acc[j] = fmaf(zc, w3s[j * F2 + c], acc[j]);
    }

    __syncthreads();
#pragma unroll
    for (int j = 0; j < F3; j++) ys[tid * 11 + j] = acc[j];
    __syncthreads();
    {
        float* og = out + (size_t)rowBase * F3;
        for (int i = tid; i < 128 * F3; i += 128) {
            int r = i / F3, j = i - r * F3;
            og[i] = ys[r * 11 + j];
        }
    }
}

// ----------------------------- launch --------------------------------------
extern "C" void kernel_launch(void* const* d_in, const int* in_sizes, int n_in,
                              void* d_out, int out_size) {
    const float* x      = (const float*)d_in[0];
    const float* w1     = (const float*)d_in[1];
    const float* b1     = (const float*)d_in[2];
    const float* gamma1 = (const float*)d_in[3];
    const float* beta1  = (const float*)d_in[4];
    const float* w2     = (const float*)d_in[5];
    const float* b2     = (const float*)d_in[6];
    const float* gamma2 = (const float*)d_in[7];
    const float* beta2  = (const float*)d_in[8];
    const float* w3     = (const float*)d_in[9];
    const float* b3     = (const float*)d_in[10];
    float* out = (float*)d_out;

    k1_mma<<<512, 128, SM1_TOTAL>>>(x, w1, b1, gamma1, beta1);
    k3_mid<<<512, 128>>>(w2, b2, gamma2, beta2);
    k5_out<<<512, 128>>>(w3, b3, out);
}

// round 8
// speedup vs baseline: 2.1126x; 1.0893x over previous
#include <cuda_runtime.h>
#include <cuda_fp16.h>
#include <cstddef>
#include <cstdint>

typedef unsigned int u32;
typedef unsigned long long ull;

#define NROWS 65536
#define F1 48
#define F2 24
#define F3 10
#define KDIM 784
#define EPSBN 1e-5f

// ----------------------------- device scratch -----------------------------
__device__ float g_Y1[(size_t)NROWS * F1];
__device__ float g_Y2[(size_t)NROWS * F2];
__device__ float g_p1s[F1 * 512];
__device__ float g_p1q[F1 * 512];
__device__ float g_p2s[F2 * 512];
__device__ float g_p2q[F2 * 512];
__device__ float g_scale1[F1], g_shift1[F1];
__device__ float g_scale2[F2], g_shift2[F2];
__device__ float g_na1, g_nm1, g_na2, g_nm2;
__device__ u32   g_k1a, g_k1b, g_k2a, g_k2b;
__device__ u32   g_cnt1 = 0, g_cnt2 = 0;

// ----------------------------- helpers ------------------------------------
// pack float2 -> fp16x2 (rounded)
__device__ __forceinline__ u32 pk_h2(float2 v) {
    u32 h;
    asm("cvt.rn.f16x2.f32 %0, %1, %2;" : "=r"(h) : "f"(v.y), "f"(v.x));
    return h;
}
// split float2 -> hi fp16x2 + lo fp16x2 (residual)
__device__ __forceinline__ void split_h2(float2 v, u32 &hi, u32 &lo) {
    asm("cvt.rn.f16x2.f32 %0, %1, %2;" : "=r"(hi) : "f"(v.y), "f"(v.x));
    float f0, f1;
    asm("{.reg .f16 a,b; mov.b32 {a,b}, %2; cvt.f32.f16 %0, a; cvt.f32.f16 %1, b;}"
        : "=f"(f0), "=f"(f1) : "r"(hi));
    asm("cvt.rn.f16x2.f32 %0, %1, %2;" : "=r"(lo) : "f"(v.y - f1), "f"(v.x - f0));
}

#define MMA_F16(c, a, b0v, b1v) \
    asm volatile("mma.sync.aligned.m16n8k16.row.col.f32.f16.f16.f32 " \
        "{%0,%1,%2,%3}, {%4,%5,%6,%7}, {%8,%9}, {%0,%1,%2,%3};" \
        : "+f"((c)[0]), "+f"((c)[1]), "+f"((c)[2]), "+f"((c)[3]) \
        : "r"((a)[0]), "r"((a)[1]), "r"((a)[2]), "r"((a)[3]), \
          "r"(b0v), "r"(b1v))

// ----------------------------- PRNG ----------------------------------------
__device__ __forceinline__ void tf2x32(u32 k0, u32 k1, u32 x0, u32 x1,
                                       u32 &o0, u32 &o1) {
    u32 k2 = k0 ^ k1 ^ 0x1BD11BDAu;
    x0 += k0; x1 += k1;
#define TF_R(r) { x0 += x1; x1 = __funnelshift_l(x1, x1, (r)); x1 ^= x0; }
    TF_R(13) TF_R(15) TF_R(26) TF_R(6)   x0 += k1; x1 += k2 + 1u;
    TF_R(17) TF_R(29) TF_R(16) TF_R(24)  x0 += k2; x1 += k0 + 2u;
    TF_R(13) TF_R(15) TF_R(26) TF_R(6)   x0 += k0; x1 += k1 + 3u;
    TF_R(17) TF_R(29) TF_R(16) TF_R(24)  x0 += k1; x1 += k2 + 4u;
    TF_R(13) TF_R(15) TF_R(26) TF_R(6)   x0 += k2; x1 += k0 + 5u;
#undef TF_R
    o0 = x0; o1 = x1;
}

__device__ __forceinline__ float jax_normal(u32 bits) {
    float u01 = __uint_as_float((bits >> 9) | 0x3f800000u) - 1.0f;
    float u   = fmaxf(-0.99999994f, fmaf(u01, 2.0f, -0.99999994f));
    float w   = -log1pf(-u * u);
    float p;
    if (w < 5.0f) {
        w -= 2.5f;
        p = 2.81022636e-08f;
        p = fmaf(p, w, 3.43273939e-07f);
        p = fmaf(p, w, -3.5233877e-06f);
        p = fmaf(p, w, -4.39150654e-06f);
        p = fmaf(p, w, 0.00021858087f);
        p = fmaf(p, w, -0.00125372503f);
        p = fmaf(p, w, -0.00417768164f);
        p = fmaf(p, w, 0.246640727f);
        p = fmaf(p, w, 1.50140941f);
    } else {
        w = sqrtf(w) - 3.0f;
        p = -0.000200214257f;
        p = fmaf(p, w, 0.000100950558f);
        p = fmaf(p, w, 0.00134934322f);
        p = fmaf(p, w, -0.00367342844f);
        p = fmaf(p, w, 0.00573950773f);
        p = fmaf(p, w, -0.0076224613f);
        p = fmaf(p, w, 0.00943887047f);
        p = fmaf(p, w, 1.00167406f);
        p = fmaf(p, w, 2.83297682f);
    }
    return 1.41421356f * (p * u);
}

// ----------------------------- K1: sync-free streaming HMMA GEMM ----------
// Y1 = x @ w1^T + b1.  CTA tile = 128 rows x 48 cols; 49 k-steps of 16.
// A fragments loaded straight from gmem (fp32 -> fp16 in regs, streaming .cs),
// B fragments via __ldg (L1-resident), split hi/lo fp16; fp32 accumulators.
__global__ void __launch_bounds__(128, 4)
k1_mma(const float* __restrict__ x, const float* __restrict__ w1,
       const float* __restrict__ b1, const float* __restrict__ gamma,
       const float* __restrict__ beta) {
    __shared__ float ys[128 * 49];
    __shared__ float bsm[F1];
    int tid = threadIdx.x;
    int lane = tid & 31, wrp = tid >> 5;
    int g = lane >> 2, t = lane & 3;
    int rowBase = blockIdx.x * 128;

    if (tid < F1) bsm[tid] = b1[tid];

    const float* xA = x + (size_t)(rowBase + wrp * 32 + g) * KDIM + t * 2;
    const float* wB = w1 + (size_t)g * KDIM + t * 2;

    float C[2][6][4];
#pragma unroll
    for (int mt = 0; mt < 2; mt++)
#pragma unroll
        for (int nt = 0; nt < 6; nt++)
#pragma unroll
            for (int e = 0; e < 4; e++) C[mt][nt][e] = 0.f;

#pragma unroll 2
    for (int ks = 0; ks < 49; ks++) {
        int ko = ks * 16;
        u32 a[2][4];
#pragma unroll
        for (int mt = 0; mt < 2; mt++) {
            const float* p = xA + mt * (16 * KDIM) + ko;
            float2 v0 = __ldcs((const float2*)p);
            float2 v1 = __ldcs((const float2*)(p + 8 * KDIM));
            float2 v2 = __ldcs((const float2*)(p + 8));
            float2 v3 = __ldcs((const float2*)(p + 8 * KDIM + 8));
            a[mt][0] = pk_h2(v0);
            a[mt][1] = pk_h2(v1);
            a[mt][2] = pk_h2(v2);
            a[mt][3] = pk_h2(v3);
        }
#pragma unroll
        for (int nt = 0; nt < 6; nt++) {
            const float* p = wB + nt * (8 * KDIM) + ko;
            float2 u0 = __ldg((const float2*)p);
            float2 u1 = __ldg((const float2*)(p + 8));
            u32 bh0, bl0, bh1, bl1;
            split_h2(u0, bh0, bl0);
            split_h2(u1, bh1, bl1);
            MMA_F16(C[0][nt], a[0], bh0, bh1);
            MMA_F16(C[1][nt], a[1], bh0, bh1);
            MMA_F16(C[0][nt], a[0], bl0, bl1);
            MMA_F16(C[1][nt], a[1], bl0, bl1);
        }
    }

    // ---- epilogue: bias, stage, stats, coalesced write ----
    int rg = lane >> 2, cg = (lane & 3) * 2;
#pragma unroll
    for (int mt = 0; mt < 2; mt++) {
        int r0 = wrp * 32 + mt * 16 + rg;
#pragma unroll
        for (int nt = 0; nt < 6; nt++) {
            int col = nt * 8 + cg;
            ys[r0 * 49 + col]           = C[mt][nt][0] + bsm[col];
            ys[r0 * 49 + col + 1]       = C[mt][nt][1] + bsm[col + 1];
            ys[(r0 + 8) * 49 + col]     = C[mt][nt][2] + bsm[col];
            ys[(r0 + 8) * 49 + col + 1] = C[mt][nt][3] + bsm[col + 1];
        }
    }
    __syncthreads();

    if (tid < F1) {                          // transposed partials [col][block]
        float s = 0.f, q = 0.f;
        for (int r = 0; r < 128; r++) {
            float v = ys[r * 49 + tid];
            s += v; q += v * v;
        }
        g_p1s[tid * 512 + blockIdx.x] = s;
        g_p1q[tid * 512 + blockIdx.x] = q;
    }
    float* yg = g_Y1 + (size_t)rowBase * F1;
#pragma unroll 4
    for (int p = 0; p < 48; p++) {
        int i = p * 128 + tid;
        int r = i / F1, cc = i - r * F1;
        yg[i] = ys[r * 49 + cc];
    }

    // ---- last-block finalize (layer-1 stats + noise consts) ----
    __shared__ u32 fin_last;
    __shared__ float fin_term[F1], fin_beta[F1];
    __threadfence();
    __syncthreads();
    if (tid == 0) fin_last = (atomicAdd(&g_cnt1, 1u) == 511u) ? 1u : 0u;
    __syncthreads();
    if (fin_last == 0u) return;
    __threadfence();

    if (tid < F1) {
        const float4* ps = (const float4*)(g_p1s + (size_t)tid * 512);
        const float4* pq = (const float4*)(g_p1q + (size_t)tid * 512);
        float s = 0.f, q = 0.f;
#pragma unroll 8
        for (int i = 0; i < 128; i++) {
            float4 a = ps[i]; s += (a.x + a.y) + (a.z + a.w);
            float4 b = pq[i]; q += (b.x + b.y) + (b.z + b.w);
        }
        float m = s / 65536.0f;
        float v = fmaxf(q / 65536.0f - m * m, 0.f);
        float ga = gamma[tid], be = beta[tid];
        float sc = ga * rsqrtf(v + EPSBN);
        g_scale1[tid] = sc;
        g_shift1[tid] = be - m * sc;
        fin_beta[tid] = be;
        fin_term[tid] = ga * ga * (v / (v + EPSBN));
    }
    __syncthreads();
    if (tid == 0) {
        float nb = 0.f;
        for (int c = 0; c < F1; c++) nb += fin_beta[c];
        float nm = nb / (float)F1;
        float S = 0.f;
        for (int c = 0; c < F1; c++) {
            float d = fin_beta[c] - nm;
            S += fin_term[c] + d * d;
        }
        float var = (65536.0f * S) / (65536.0f * (float)F1 - 1.0f);
        float sdev = sqrtf(var);
        u32 ka, kb2, na, nbk;
        tf2x32(0u, 1234u, 0u, 0u, ka, kb2);
        tf2x32(0u, 1234u, 0u, 1u, na, nbk);
        u32 u0, u1;
        tf2x32(ka, kb2, 0u, 0u, u0, u1);
        u32 bits = u0 ^ u1;
        float u01 = __uint_as_float((bits >> 9) | 0x3f800000u) - 1.0f;
        float uu = fmaxf(1.0f, u01 + 1.0f);
        g_na1 = sdev * uu;
        g_nm1 = nm;
        g_k1a = na; g_k1b = nbk;
        g_cnt1 = 0u;
    }
}

// ----------------------------- K3: BN1+noise+ReLU -> GEMM2 + fin2 ---------
__global__ void __launch_bounds__(128) k3_mid(const float* __restrict__ w2,
                                              const float* __restrict__ b2,
                                              const float* __restrict__ gamma,
                                              const float* __restrict__ beta) {
    __shared__ float ys[128 * 49];
    __shared__ float w2s[F2 * F1];
    __shared__ float b2s[F2];
    __shared__ float sc1[F1], sh1[F1];
    __shared__ float wrs[4 * F2], wrq[4 * F2];
    int tid = threadIdx.x;
    int rowBase = blockIdx.x * 128;

    for (int i = tid; i < F2 * F1; i += 128) w2s[i] = w2[i];
    if (tid < F2) b2s[tid] = b2[tid];
    if (tid < F1) { sc1[tid] = g_scale1[tid]; sh1[tid] = g_shift1[tid]; }
    {
        const float* yg = g_Y1 + (size_t)rowBase * F1;
        for (int i = tid; i < 128 * F1; i += 128) {
            int r = i / F1, c = i - r * F1;
            ys[r * 49 + c] = yg[i];
        }
    }
    __syncthreads();

    float na = g_na1, nm = g_nm1;
    u32 ka = g_k1a, kb = g_k1b;
    u32 base = (u32)(rowBase + tid) * (u32)F1;

    float acc[F2];
#pragma unroll
    for (int j = 0; j < F2; j++) acc[j] = b2s[j];

#pragma unroll 4
    for (int c = 0; c < F1; c++) {
        float h = fmaf(ys[tid * 49 + c], sc1[c], sh1[c]);
        u32 o0, o1;
        tf2x32(ka, kb, 0u, base + (u32)c, o0, o1);
        float noi = fmaf(na, jax_normal(o0 ^ o1), nm);
        float zc = fmaxf(h + noi, 0.f);
#pragma unroll
        for (int j = 0; j < F2; j++)
            acc[j] = fmaf(zc, w2s[j * F1 + c], acc[j]);
    }

    int lane = tid & 31, wrp = tid >> 5;
#pragma unroll
    for (int j = 0; j < F2; j++) {
        float sv = acc[j], qv = acc[j] * acc[j];
#pragma unroll
        for (int off = 16; off > 0; off >>= 1) {
            sv += __shfl_down_sync(0xffffffffu, sv, off);
            qv += __shfl_down_sync(0xffffffffu, qv, off);
        }
        if (lane == 0) { wrs[wrp * F2 + j] = sv; wrq[wrp * F2 + j] = qv; }
    }

    __syncthreads();
    if (tid < F2) {                          // transposed partials [col][block]
        g_p2s[tid * 512 + blockIdx.x] =
            wrs[tid] + wrs[F2 + tid] + wrs[2 * F2 + tid] + wrs[3 * F2 + tid];
        g_p2q[tid * 512 + blockIdx.x] =
            wrq[tid] + wrq[F2 + tid] + wrq[2 * F2 + tid] + wrq[3 * F2 + tid];
    }

#pragma unroll
    for (int j = 0; j < F2; j++) ys[tid * 25 + j] = acc[j];
    __syncthreads();
    {
        float* yg2 = g_Y2 + (size_t)rowBase * F2;
        for (int i = tid; i < 128 * F2; i += 128) {
            int r = i / F2, j = i - r * F2;
            yg2[i] = ys[r * 25 + j];
        }
    }

    // ---- last-block finalize (layer-2 stats + noise consts) ----
    __shared__ u32 fin_last;
    __shared__ float fin_term[F2], fin_beta[F2];
    __threadfence();
    __syncthreads();
    if (tid == 0) fin_last = (atomicAdd(&g_cnt2, 1u) == 511u) ? 1u : 0u;
    __syncthreads();
    if (fin_last == 0u) return;
    __threadfence();

    if (tid < F2) {
        const float4* ps = (const float4*)(g_p2s + (size_t)tid * 512);
        const float4* pq = (const float4*)(g_p2q + (size_t)tid * 512);
        float s = 0.f, q = 0.f;
#pragma unroll 8
        for (int i = 0; i < 128; i++) {
            float4 a = ps[i]; s += (a.x + a.y) + (a.z + a.w);
            float4 b = pq[i]; q += (b.x + b.y) + (b.z + b.w);
        }
        float m = s / 65536.0f;
        float v = fmaxf(q / 65536.0f - m * m, 0.f);
        float ga = gamma[tid], be = beta[tid];
        float sc = ga * rsqrtf(v + EPSBN);
        g_scale2[tid] = sc;
        g_shift2[tid] = be - m * sc;
        fin_beta[tid] = be;
        fin_term[tid] = ga * ga * (v / (v + EPSBN));
    }
    __syncthreads();
    if (tid == 0) {
        float nb = 0.f;
        for (int c = 0; c < F2; c++) nb += fin_beta[c];
        float nm2 = nb / (float)F2;
        float S = 0.f;
        for (int c = 0; c < F2; c++) {
            float d = fin_beta[c] - nm2;
            S += fin_term[c] + d * d;
        }
        float var = (65536.0f * S) / (65536.0f * (float)F2 - 1.0f);
        float sdev = sqrtf(var);
        u32 ka2, kb2, na2, nbk2;
        tf2x32(0u, 5678u, 0u, 0u, ka2, kb2);
        tf2x32(0u, 5678u, 0u, 1u, na2, nbk2);
        u32 u0, u1;
        tf2x32(ka2, kb2, 0u, 0u, u0, u1);
        u32 bits = u0 ^ u1;
        float u01 = __uint_as_float((bits >> 9) | 0x3f800000u) - 1.0f;
        float uu = fmaxf(1.0f, u01 + 1.0f);
        g_na2 = sdev * uu;
        g_nm2 = nm2;
        g_k2a = na2; g_k2b = nbk2;
        g_cnt2 = 0u;
    }
}

// ----------------------------- K5: BN2+noise+ReLU -> GEMM3 -> out ---------
__global__ void __launch_bounds__(128) k5_out(const float* __restrict__ w3,
                                              const float* __restrict__ b3,
                                              float* __restrict__ out) {
    __shared__ float ys[128 * 25];
    __shared__ float w3s[F3 * F2];
    __shared__ float b3s[F3];
    __shared__ float sc2[F2], sh2[F2];
    int tid = threadIdx.x;
    int rowBase = blockIdx.x * 128;

    for (int i = tid; i < F3 * F2; i += 128) w3s[i] = w3[i];
    if (tid < F3) b3s[tid] = b3[tid];
    if (tid < F2) { sc2[tid] = g_scale2[tid]; sh2[tid] = g_shift2[tid]; }
    {
        const float* yg = g_Y2 + (size_t)rowBase * F2;
        for (int i = tid; i < 128 * F2; i += 128) {
            int r = i / F2, c = i - r * F2;
            ys[r * 25 + c] = yg[i];
        }
    }
    __syncthreads();

    float na = g_na2, nm = g_nm2;
    u32 ka = g_k2a, kb = g_k2b;
    u32 base = (u32)(rowBase + tid) * (u32)F2;

    float acc[F3];
#pragma unroll
    for (int j = 0; j < F3; j++) acc[j] = b3s[j];

#pragma unroll 4
    for (int c = 0; c < F2; c++) {
        float h = fmaf(ys[tid * 25 + c], sc2[c], sh2[c]);
        u32 o0, o1;
        tf2x32(ka, kb, 0u, base + (u32)c, o0, o1);
        float noi = fmaf(na, jax_normal(o0 ^ o1), nm);
        float zc = fmaxf(h + noi, 0.f);
#pragma unroll
        for (int j = 0; j < F3; j++)
            acc[j] = fmaf(zc, w3s[j * F2 + c], acc[j]);
    }

    __syncthreads();
#pragma unroll
    for (int j = 0; j < F3; j++) ys[tid * 11 + j] = acc[j];
    __syncthreads();
    {
        float* og = out + (size_t)rowBase * F3;
        for (int i = tid; i < 128 * F3; i += 128) {
            int r = i / F3, j = i - r * F3;
            og[i] = ys[r * 11 + j];
        }
    }
}

// ----------------------------- launch --------------------------------------
extern "C" void kernel_launch(void* const* d_in, const int* in_sizes, int n_in,
                              void* d_out, int out_size) {
    const float* x      = (const float*)d_in[0];
    const float* w1     = (const float*)d_in[1];
    const float* b1     = (const float*)d_in[2];
    const float* gamma1 = (const float*)d_in[3];
    const float* beta1  = (const float*)d_in[4];
    const float* w2     = (const float*)d_in[5];
    const float* b2     = (const float*)d_in[6];
    const float* gamma2 = (const float*)d_in[7];
    const float* beta2  = (const float*)d_in[8];
    const float* w3     = (const float*)d_in[9];
    const float* b3     = (const float*)d_in[10];
    float* out = (float*)d_out;

    k1_mma<<<512, 128>>>(x, w1, b1, gamma1, beta1);
    k3_mid<<<512, 128>>>(w2, b2, gamma2, beta2);
    k5_out<<<512, 128>>>(w3, b3, out);
}

// round 9
// speedup vs baseline: 2.3445x; 1.1098x over previous
#include <cuda_runtime.h>
#include <cuda_fp16.h>
#include <cstddef>
#include <cstdint>

typedef unsigned int u32;
typedef unsigned long long ull;

#define NROWS 65536
#define F1 48
#define F2 24
#define F3 10
#define KDIM 784
#define EPSBN 1e-5f

// ----------------------------- device scratch -----------------------------
__device__ float g_Y1[(size_t)NROWS * F1];
__device__ float g_Y2[(size_t)NROWS * F2];
__device__ uint4 g_w1p[F1 * 49 * 4];      // packed split-fp16 w1 fragments
__device__ float g_p1s[F1 * 512];
__device__ float g_p1q[F1 * 512];
__device__ float g_p2s[F2 * 512];
__device__ float g_p2q[F2 * 512];
__device__ float g_scale1[F1], g_shift1[F1];
__device__ float g_scale2[F2], g_shift2[F2];
__device__ float g_na1, g_nm1, g_na2, g_nm2;
__device__ u32   g_k1a, g_k1b, g_k2a, g_k2b;
__device__ u32   g_cnt1 = 0, g_cnt2 = 0;

// ----------------------------- helpers ------------------------------------
// pack float2 -> fp16x2 (rounded)
__device__ __forceinline__ u32 pk_h2(float2 v) {
    u32 h;
    asm("cvt.rn.f16x2.f32 %0, %1, %2;" : "=r"(h) : "f"(v.y), "f"(v.x));
    return h;
}
// split float2 -> hi fp16x2 + lo fp16x2 (residual)
__device__ __forceinline__ void split_h2(float2 v, u32 &hi, u32 &lo) {
    asm("cvt.rn.f16x2.f32 %0, %1, %2;" : "=r"(hi) : "f"(v.y), "f"(v.x));
    float f0, f1;
    asm("{.reg .f16 a,b; mov.b32 {a,b}, %2; cvt.f32.f16 %0, a; cvt.f32.f16 %1, b;}"
        : "=f"(f0), "=f"(f1) : "r"(hi));
    asm("cvt.rn.f16x2.f32 %0, %1, %2;" : "=r"(lo) : "f"(v.y - f1), "f"(v.x - f0));
}

#define MMA_F16(c, a, b0v, b1v) \
    asm volatile("mma.sync.aligned.m16n8k16.row.col.f32.f16.f16.f32 " \
        "{%0,%1,%2,%3}, {%4,%5,%6,%7}, {%8,%9}, {%0,%1,%2,%3};" \
        : "+f"((c)[0]), "+f"((c)[1]), "+f"((c)[2]), "+f"((c)[3]) \
        : "r"((a)[0]), "r"((a)[1]), "r"((a)[2]), "r"((a)[3]), \
          "r"(b0v), "r"(b1v))

// ----------------------------- PRNG ----------------------------------------
__device__ __forceinline__ void tf2x32(u32 k0, u32 k1, u32 x0, u32 x1,
                                       u32 &o0, u32 &o1) {
    u32 k2 = k0 ^ k1 ^ 0x1BD11BDAu;
    x0 += k0; x1 += k1;
#define TF_R(r) { x0 += x1; x1 = __funnelshift_l(x1, x1, (r)); x1 ^= x0; }
    TF_R(13) TF_R(15) TF_R(26) TF_R(6)   x0 += k1; x1 += k2 + 1u;
    TF_R(17) TF_R(29) TF_R(16) TF_R(24)  x0 += k2; x1 += k0 + 2u;
    TF_R(13) TF_R(15) TF_R(26) TF_R(6)   x0 += k0; x1 += k1 + 3u;
    TF_R(17) TF_R(29) TF_R(16) TF_R(24)  x0 += k1; x1 += k2 + 4u;
    TF_R(13) TF_R(15) TF_R(26) TF_R(6)   x0 += k2; x1 += k0 + 5u;
#undef TF_R
    o0 = x0; o1 = x1;
}

__device__ __forceinline__ float jax_normal(u32 bits) {
    float u01 = __uint_as_float((bits >> 9) | 0x3f800000u) - 1.0f;
    float u   = fmaxf(-0.99999994f, fmaf(u01, 2.0f, -0.99999994f));
    float w   = -log1pf(-u * u);
    float p;
    if (w < 5.0f) {
        w -= 2.5f;
        p = 2.81022636e-08f;
        p = fmaf(p, w, 3.43273939e-07f);
        p = fmaf(p, w, -3.5233877e-06f);
        p = fmaf(p, w, -4.39150654e-06f);
        p = fmaf(p, w, 0.00021858087f);
        p = fmaf(p, w, -0.00125372503f);
        p = fmaf(p, w, -0.00417768164f);
        p = fmaf(p, w, 0.246640727f);
        p = fmaf(p, w, 1.50140941f);
    } else {
        w = sqrtf(w) - 3.0f;
        p = -0.000200214257f;
        p = fmaf(p, w, 0.000100950558f);
        p = fmaf(p, w, 0.00134934322f);
        p = fmaf(p, w, -0.00367342844f);
        p = fmaf(p, w, 0.00573950773f);
        p = fmaf(p, w, -0.0076224613f);
        p = fmaf(p, w, 0.00943887047f);
        p = fmaf(p, w, 1.00167406f);
        p = fmaf(p, w, 2.83297682f);
    }
    return 1.41421356f * (p * u);
}

// ----------------------------- K0: pack w1 fragments ----------------------
// For fragment slot (r, ks, t): uint4 { hi(k=2t), hi(k=2t+8), lo(k=2t), lo(k=2t+8) }
__global__ void __launch_bounds__(128) k0_pack(const float* __restrict__ w1) {
    int e = blockIdx.x * 128 + threadIdx.x;
    if (e >= F1 * 49 * 4) return;
    int t = e & 3;
    int ks = (e >> 2) % 49;
    int r = e / 196;
    const float* p = w1 + (size_t)r * KDIM + ks * 16 + t * 2;
    float2 u0 = *(const float2*)p;
    float2 u1 = *(const float2*)(p + 8);
    u32 h0, l0, h1, l1;
    split_h2(u0, h0, l0);
    split_h2(u1, h1, l1);
    g_w1p[e] = make_uint4(h0, h1, l0, l1);
}

// ----------------------------- K1: streaming HMMA GEMM (packed B) ---------
// Y1 = x @ w1^T + b1.  CTA tile = 128 rows x 48 cols; 49 k-steps of 16.
// A: direct gmem float2 loads (.cs), prefetched one k-step ahead.
// B: one uint4 L1-hit per (nt, k-step) from g_w1p.  fp32 accumulators.
__global__ void __launch_bounds__(128, 4)
k1_mma(const float* __restrict__ x, const float* __restrict__ b1,
       const float* __restrict__ gamma, const float* __restrict__ beta) {
    __shared__ float ys[128 * 49];
    __shared__ float bsm[F1];
    int tid = threadIdx.x;
    int lane = tid & 31, wrp = tid >> 5;
    int g = lane >> 2, t = lane & 3;
    int rowBase = blockIdx.x * 128;

    if (tid < F1) bsm[tid] = b1[tid];

    const float* xA = x + (size_t)(rowBase + wrp * 32 + g) * KDIM + t * 2;
    const uint4* wp = g_w1p + g * 196 + t;    // + nt*1568 + ks*4

    float C[2][6][4];
#pragma unroll
    for (int mt = 0; mt < 2; mt++)
#pragma unroll
        for (int nt = 0; nt < 6; nt++)
#pragma unroll
            for (int e = 0; e < 4; e++) C[mt][nt][e] = 0.f;

    float2 n0, n1, n2, n3, m0, m1, m2, m3;   // prefetched raw A
#define LDA(ks, mt, v0, v1, v2, v3) { \
    const float* p_ = xA + (mt) * (16 * KDIM) + (ks) * 16; \
    v0 = __ldcs((const float2*)p_); \
    v1 = __ldcs((const float2*)(p_ + 8 * KDIM)); \
    v2 = __ldcs((const float2*)(p_ + 8)); \
    v3 = __ldcs((const float2*)(p_ + 8 * KDIM + 8)); }

    LDA(0, 0, n0, n1, n2, n3)
    LDA(0, 1, m0, m1, m2, m3)

#pragma unroll 1
    for (int ks = 0; ks < 49; ks++) {
        u32 a0[4], a1[4];
        a0[0] = pk_h2(n0); a0[1] = pk_h2(n1); a0[2] = pk_h2(n2); a0[3] = pk_h2(n3);
        a1[0] = pk_h2(m0); a1[1] = pk_h2(m1); a1[2] = pk_h2(m2); a1[3] = pk_h2(m3);
        if (ks < 48) {
            LDA(ks + 1, 0, n0, n1, n2, n3)
            LDA(ks + 1, 1, m0, m1, m2, m3)
        }
#pragma unroll
        for (int nt = 0; nt < 6; nt++) {
            uint4 w = __ldg(wp + nt * 1568 + ks * 4);
            MMA_F16(C[0][nt], a0, w.x, w.y);
            MMA_F16(C[1][nt], a1, w.x, w.y);
            MMA_F16(C[0][nt], a0, w.z, w.w);
            MMA_F16(C[1][nt], a1, w.z, w.w);
        }
    }
#undef LDA

    // ---- epilogue: bias, stage, stats, coalesced write ----
    int rg = lane >> 2, cg = (lane & 3) * 2;
#pragma unroll
    for (int mt = 0; mt < 2; mt++) {
        int r0 = wrp * 32 + mt * 16 + rg;
#pragma unroll
        for (int nt = 0; nt < 6; nt++) {
            int col = nt * 8 + cg;
            ys[r0 * 49 + col]           = C[mt][nt][0] + bsm[col];
            ys[r0 * 49 + col + 1]       = C[mt][nt][1] + bsm[col + 1];
            ys[(r0 + 8) * 49 + col]     = C[mt][nt][2] + bsm[col];
            ys[(r0 + 8) * 49 + col + 1] = C[mt][nt][3] + bsm[col + 1];
        }
    }
    __syncthreads();

    if (tid < F1) {                          // transposed partials [col][block]
        float s = 0.f, q = 0.f;
        for (int r = 0; r < 128; r++) {
            float v = ys[r * 49 + tid];
            s += v; q += v * v;
        }
        g_p1s[tid * 512 + blockIdx.x] = s;
        g_p1q[tid * 512 + blockIdx.x] = q;
    }
    float* yg = g_Y1 + (size_t)rowBase * F1;
#pragma unroll 4
    for (int p = 0; p < 48; p++) {
        int i = p * 128 + tid;
        int r = i / F1, cc = i - r * F1;
        yg[i] = ys[r * 49 + cc];
    }

    // ---- last-block finalize (layer-1 stats + noise consts) ----
    __shared__ u32 fin_last;
    __shared__ float fin_term[F1], fin_beta[F1];
    __threadfence();
    __syncthreads();
    if (tid == 0) fin_last = (atomicAdd(&g_cnt1, 1u) == 511u) ? 1u : 0u;
    __syncthreads();
    if (fin_last == 0u) return;
    __threadfence();

    if (tid < F1) {
        const float4* ps = (const float4*)(g_p1s + (size_t)tid * 512);
        const float4* pq = (const float4*)(g_p1q + (size_t)tid * 512);
        float s = 0.f, q = 0.f;
#pragma unroll 8
        for (int i = 0; i < 128; i++) {
            float4 a = ps[i]; s += (a.x + a.y) + (a.z + a.w);
            float4 b = pq[i]; q += (b.x + b.y) + (b.z + b.w);
        }
        float m = s / 65536.0f;
        float v = fmaxf(q / 65536.0f - m * m, 0.f);
        float ga = gamma[tid], be = beta[tid];
        float sc = ga * rsqrtf(v + EPSBN);
        g_scale1[tid] = sc;
        g_shift1[tid] = be - m * sc;
        fin_beta[tid] = be;
        fin_term[tid] = ga * ga * (v / (v + EPSBN));
    }
    __syncthreads();
    if (tid == 0) {
        float nb = 0.f;
        for (int c = 0; c < F1; c++) nb += fin_beta[c];
        float nm = nb / (float)F1;
        float S = 0.f;
        for (int c = 0; c < F1; c++) {
            float d = fin_beta[c] - nm;
            S += fin_term[c] + d * d;
        }
        float var = (65536.0f * S) / (65536.0f * (float)F1 - 1.0f);
        float sdev = sqrtf(var);
        u32 ka, kb2, na, nbk;
        tf2x32(0u, 1234u, 0u, 0u, ka, kb2);
        tf2x32(0u, 1234u, 0u, 1u, na, nbk);
        u32 u0, u1;
        tf2x32(ka, kb2, 0u, 0u, u0, u1);
        u32 bits = u0 ^ u1;
        float u01 = __uint_as_float((bits >> 9) | 0x3f800000u) - 1.0f;
        float uu = fmaxf(1.0f, u01 + 1.0f);
        g_na1 = sdev * uu;
        g_nm1 = nm;
        g_k1a = na; g_k1b = nbk;
        g_cnt1 = 0u;
    }
}

// ----------------------------- K3: BN1+noise+ReLU -> GEMM2 + fin2 ---------
__global__ void __launch_bounds__(128) k3_mid(const float* __restrict__ w2,
                                              const float* __restrict__ b2,
                                              const float* __restrict__ gamma,
                                              const float* __restrict__ beta) {
    __shared__ float ys[128 * 49];
    __shared__ float w2s[F2 * F1];
    __shared__ float b2s[F2];
    __shared__ float sc1[F1], sh1[F1];
    __shared__ float wrs[4 * F2], wrq[4 * F2];
    int tid = threadIdx.x;
    int rowBase = blockIdx.x * 128;

    for (int i = tid; i < F2 * F1; i += 128) w2s[i] = w2[i];
    if (tid < F2) b2s[tid] = b2[tid];
    if (tid < F1) { sc1[tid] = g_scale1[tid]; sh1[tid] = g_shift1[tid]; }
    {
        const float* yg = g_Y1 + (size_t)rowBase * F1;
        for (int i = tid; i < 128 * F1; i += 128) {
            int r = i / F1, c = i - r * F1;
            ys[r * 49 + c] = yg[i];
        }
    }
    __syncthreads();

    float na = g_na1, nm = g_nm1;
    u32 ka = g_k1a, kb = g_k1b;
    u32 base = (u32)(rowBase + tid) * (u32)F1;

    float acc[F2];
#pragma unroll
    for (int j = 0; j < F2; j++) acc[j] = b2s[j];

#pragma unroll 4
    for (int c = 0; c < F1; c++) {
        float h = fmaf(ys[tid * 49 + c], sc1[c], sh1[c]);
        u32 o0, o1;
        tf2x32(ka, kb, 0u, base + (u32)c, o0, o1);
        float noi = fmaf(na, jax_normal(o0 ^ o1), nm);
        float zc = fmaxf(h + noi, 0.f);
#pragma unroll
        for (int j = 0; j < F2; j++)
            acc[j] = fmaf(zc, w2s[j * F1 + c], acc[j]);
    }

    int lane = tid & 31, wrp = tid >> 5;
#pragma unroll
    for (int j = 0; j < F2; j++) {
        float sv = acc[j], qv = acc[j] * acc[j];
#pragma unroll
        for (int off = 16; off > 0; off >>= 1) {
            sv += __shfl_down_sync(0xffffffffu, sv, off);
            qv += __shfl_down_sync(0xffffffffu, qv, off);
        }
        if (lane == 0) { wrs[wrp * F2 + j] = sv; wrq[wrp * F2 + j] = qv; }
    }

    __syncthreads();
    if (tid < F2) {                          // transposed partials [col][block]
        g_p2s[tid * 512 + blockIdx.x] =
            wrs[tid] + wrs[F2 + tid] + wrs[2 * F2 + tid] + wrs[3 * F2 + tid];
        g_p2q[tid * 512 + blockIdx.x] =
            wrq[tid] + wrq[F2 + tid] + wrq[2 * F2 + tid] + wrq[3 * F2 + tid];
    }

#pragma unroll
    for (int j = 0; j < F2; j++) ys[tid * 25 + j] = acc[j];
    __syncthreads();
    {
        float* yg2 = g_Y2 + (size_t)rowBase * F2;
        for (int i = tid; i < 128 * F2; i += 128) {
            int r = i / F2, j = i - r * F2;
            yg2[i] = ys[r * 25 + j];
        }
    }

    // ---- last-block finalize (layer-2 stats + noise consts) ----
    __shared__ u32 fin_last;
    __shared__ float fin_term[F2], fin_beta[F2];
    __threadfence();
    __syncthreads();
    if (tid == 0) fin_last = (atomicAdd(&g_cnt2, 1u) == 511u) ? 1u : 0u;
    __syncthreads();
    if (fin_last == 0u) return;
    __threadfence();

    if (tid < F2) {
        const float4* ps = (const float4*)(g_p2s + (size_t)tid * 512);
        const float4* pq = (const float4*)(g_p2q + (size_t)tid * 512);
        float s = 0.f, q = 0.f;
#pragma unroll 8
        for (int i = 0; i < 128; i++) {
            float4 a = ps[i]; s += (a.x + a.y) + (a.z + a.w);
            float4 b = pq[i]; q += (b.x + b.y) + (b.z + b.w);
        }
        float m = s / 65536.0f;
        float v = fmaxf(q / 65536.0f - m * m, 0.f);
        float ga = gamma[tid], be = beta[tid];
        float sc = ga * rsqrtf(v + EPSBN);
        g_scale2[tid] = sc;
        g_shift2[tid] = be - m * sc;
        fin_beta[tid] = be;
        fin_term[tid] = ga * ga * (v / (v + EPSBN));
    }
    __syncthreads();
    if (tid == 0) {
        float nb = 0.f;
        for (int c = 0; c < F2; c++) nb += fin_beta[c];
        float nm2 = nb / (float)F2;
        float S = 0.f;
        for (int c = 0; c < F2; c++) {
            float d = fin_beta[c] - nm2;
            S += fin_term[c] + d * d;
        }
        float var = (65536.0f * S) / (65536.0f * (float)F2 - 1.0f);
        float sdev = sqrtf(var);
        u32 ka2, kb2, na2, nbk2;
        tf2x32(0u, 5678u, 0u, 0u, ka2, kb2);
        tf2x32(0u, 5678u, 0u, 1u, na2, nbk2);
        u32 u0, u1;
        tf2x32(ka2, kb2, 0u, 0u, u0, u1);
        u32 bits = u0 ^ u1;
        float u01 = __uint_as_float((bits >> 9) | 0x3f800000u) - 1.0f;
        float uu = fmaxf(1.0f, u01 + 1.0f);
        g_na2 = sdev * uu;
        g_nm2 = nm2;
        g_k2a = na2; g_k2b = nbk2;
        g_cnt2 = 0u;
    }
}

// ----------------------------- K5: BN2+noise+ReLU -> GEMM3 -> out ---------
__global__ void __launch_bounds__(128) k5_out(const float* __restrict__ w3,
                                              const float* __restrict__ b3,
                                              float* __restrict__ out) {
    __shared__ float ys[128 * 25];
    __shared__ float w3s[F3 * F2];
    __shared__ float b3s[F3];
    __shared__ float sc2[F2], sh2[F2];
    int tid = threadIdx.x;
    int rowBase = blockIdx.x * 128;

    for (int i = tid; i < F3 * F2; i += 128) w3s[i] = w3[i];
    if (tid < F3) b3s[tid] = b3[tid];
    if (tid < F2) { sc2[tid] = g_scale2[tid]; sh2[tid] = g_shift2[tid]; }
    {
        const float* yg = g_Y2 + (size_t)rowBase * F2;
        for (int i = tid; i < 128 * F2; i += 128) {
            int r = i / F2, c = i - r * F2;
            ys[r * 25 + c] = yg[i];
        }
    }
    __syncthreads();

    float na = g_na2, nm = g_nm2;
    u32 ka = g_k2a, kb = g_k2b;
    u32 base = (u32)(rowBase + tid) * (u32)F2;

    float acc[F3];
#pragma unroll
    for (int j = 0; j < F3; j++) acc[j] = b3s[j];

#pragma unroll 4
    for (int c = 0; c < F2; c++) {
        float h = fmaf(ys[tid * 25 + c], sc2[c], sh2[c]);
        u32 o0, o1;
        tf2x32(ka, kb, 0u, base + (u32)c, o0, o1);
        float noi = fmaf(na, jax_normal(o0 ^ o1), nm);
        float zc = fmaxf(h + noi, 0.f);
#pragma unroll
        for (int j = 0; j < F3; j++)
            acc[j] = fmaf(zc, w3s[j * F2 + c], acc[j]);
    }

    __syncthreads();
#pragma unroll
    for (int j = 0; j < F3; j++) ys[tid * 11 + j] = acc[j];
    __syncthreads();
    {
        float* og = out + (size_t)rowBase * F3;
        for (int i = tid; i < 128 * F3; i += 128) {
            int r = i / F3, j = i - r * F3;
            og[i] = ys[r * 11 + j];
        }
    }
}

// ----------------------------- launch --------------------------------------
extern "C" void kernel_launch(void* const* d_in, const int* in_sizes, int n_in,
                              void* d_out, int out_size) {
    const float* x      = (const float*)d_in[0];
    const float* w1     = (const float*)d_in[1];
    const float* b1     = (const float*)d_in[2];
    const float* gamma1 = (const float*)d_in[3];
    const float* beta1  = (const float*)d_in[4];
    const float* w2     = (const float*)d_in[5];
    const float* b2     = (const float*)d_in[6];
    const float* gamma2 = (const float*)d_in[7];
    const float* beta2  = (const float*)d_in[8];
    const float* w3     = (const float*)d_in[9];
    const float* b3     = (const float*)d_in[10];
    float* out = (float*)d_out;

    k0_pack<<<74, 128>>>(w1);
    k1_mma<<<512, 128>>>(x, b1, gamma1, beta1);
    k3_mid<<<512, 128>>>(w2, b2, gamma2, beta2);
    k5_out<<<512, 128>>>(w3, b3, out);
}